// round 5
// baseline (speedup 1.0000x reference)
#include <cuda_runtime.h>
#include <cuda_bf16.h>
#include <mma.h>
#include <math.h>

using namespace nvcuda;

// ---------------- problem constants ----------------
#define BB 32
#define SS 197
#define EE 768
#define HH 12
#define DHH 64
#define FF_ 2048
#define LL 4
#define CC 1000
#define BS (BB * SS)   // 6304
#define LN_EPS 1e-5f

// ---------------- scratch (device globals; allocation-free rule) ------------
__device__ float g_h   [BS * EE];
__device__ float g_xn  [BS * EE];
__device__ float g_q   [HH * BS * DHH];
__device__ float g_k   [HH * BS * DHH];
__device__ float g_v   [HH * BS * DHH];
__device__ float g_att [BB * HH * SS * SS];
__device__ float g_o   [BS * EE];
__device__ float g_res1[BS * EE];
__device__ float g_ff  [BS * FF_];

// ---------------- layernorm: one block per row (E=768) ----------------------
__global__ void layernorm_kernel(const float* __restrict__ x,
                                 const float* __restrict__ w,
                                 const float* __restrict__ b,
                                 float* __restrict__ out) {
    int row = blockIdx.x;
    const float* xr = x + (long long)row * EE;
    float* orow = out + (long long)row * EE;
    int tid = threadIdx.x;  // 256

    float s = 0.f, s2 = 0.f;
    #pragma unroll
    for (int i = tid; i < EE; i += 256) {
        float v = xr[i];
        s += v; s2 += v * v;
    }
    __shared__ float rs[256], rs2[256];
    rs[tid] = s; rs2[tid] = s2;
    __syncthreads();
    for (int st = 128; st > 0; st >>= 1) {
        if (tid < st) { rs[tid] += rs[tid + st]; rs2[tid] += rs2[tid + st]; }
        __syncthreads();
    }
    float mu = rs[0] * (1.f / EE);
    float var = rs2[0] * (1.f / EE) - mu * mu;
    float rstd = rsqrtf(var + LN_EPS);
    #pragma unroll
    for (int i = tid; i < EE; i += 256) {
        orow[i] = (xr[i] - mu) * rstd * w[i] + b[i];
    }
}

// ---------------- attention softmax: one block per row (len 197) -------------
__global__ void att_softmax_kernel(float* __restrict__ att) {
    long long row = blockIdx.x;
    float* r = att + row * (long long)SS;
    int tid = threadIdx.x;  // 128
    __shared__ float red[128];

    float m = -1e30f;
    for (int i = tid; i < SS; i += 128) m = fmaxf(m, r[i]);
    red[tid] = m; __syncthreads();
    for (int st = 64; st > 0; st >>= 1) {
        if (tid < st) red[tid] = fmaxf(red[tid], red[tid + st]);
        __syncthreads();
    }
    m = red[0];
    __syncthreads();

    float sum = 0.f;
    for (int i = tid; i < SS; i += 128) {
        float e = expf(r[i] - m);
        r[i] = e; sum += e;
    }
    red[tid] = sum; __syncthreads();
    for (int st = 64; st > 0; st >>= 1) {
        if (tid < st) red[tid] += red[tid + st];
        __syncthreads();
    }
    float inv = 1.f / red[0];
    for (int i = tid; i < SS; i += 128) r[i] *= inv;
}

// ---------------- TF32 TC GEMM: 128xBNT tile, BK=16, double-buffered --------
// tf32 conversion done ONCE during smem staging (idempotent rounding), so the
// inner MMA loop has no cvt ops. Register-prefetched ping-pong smem pipeline.
// EPI: 0: C=alpha*acc  1: C=gelu(acc+bias)  2: C=acc+D  3: C=acc+bias+D
// TRANSB: logical B[k][n] stored as Bg[n][k] (A @ B^T).
template <int EPI, bool TRANSB, int BNT>
__global__ __launch_bounds__(256)
void tc_gemm_kernel(const float* __restrict__ A, const float* __restrict__ Bm,
                    float* __restrict__ Cm,
                    const float* __restrict__ bias, const float* __restrict__ Dm,
                    int M, int N, int K, int lda, int ldb, int ldc,
                    long long sA1, long long sA2, long long sB1, long long sB2,
                    long long sC1, long long sC2, int innerB, float alpha) {
    constexpr int BM = 128, BK = 16;
    constexpr int WCOLS = (BNT == 128) ? 4 : 2;       // warps along n
    constexpr int WARP_M = (BNT == 128) ? 64 : 32;    // warp tile m
    constexpr int WARP_N = 32;                        // warp tile n
    constexpr int AF = WARP_M / 16;                   // 4 or 2
    constexpr int BF = WARP_N / 16;                   // 2
    constexpr int LDA = BK + 4;                       // 20
    constexpr int LDB = BNT + 4;                      // 132 / 68
    constexpr int LDST = 68;                          // staging ld (64-wide)
    constexpr int A_EL = BM * BK / 256;               // 8
    constexpr int B_EL = BK * BNT / 256;              // 8 / 4
    constexpr int STAGE = BM * LDA + BK * LDB;
    constexpr int SMEM_FLOATS =
        (2 * STAGE > BM * LDST) ? 2 * STAGE : BM * LDST;

    int zo = blockIdx.z / innerB, zi = blockIdx.z % innerB;
    A  += zo * sA1 + zi * sA2;
    Bm += zo * sB1 + zi * sB2;
    long long coff = zo * sC1 + zi * sC2;
    Cm += coff;
    const float* Dp = (EPI == 2 || EPI == 3) ? (Dm + coff) : nullptr;

    const int m0 = blockIdx.y * BM, n0 = blockIdx.x * BNT;

    __shared__ __align__(16) float smem[SMEM_FLOATS];

    int tid = threadIdx.x;
    int wid = tid >> 5, lane = tid & 31;
    int wm = wid % (8 / WCOLS);
    int wn = wid / (8 / WCOLS);

    wmma::fragment<wmma::accumulator, 16, 16, 8, float> acc[AF][BF];
    #pragma unroll
    for (int i = 0; i < AF; i++)
        #pragma unroll
        for (int j = 0; j < BF; j++)
            wmma::fill_fragment(acc[i][j], 0.f);

    float ra[A_EL], rb[B_EL];

    // ---- copy helpers (predicated, coalesced along fastest dim) ----
    auto loadA = [&](int k0) {
        #pragma unroll
        for (int e = 0; e < A_EL; e++) {
            int i = tid + e * 256;
            int m = i >> 4, k = i & 15;
            int gm = m0 + m, gk = k0 + k;
            ra[e] = (gm < M && gk < K) ? A[(long long)gm * lda + gk] : 0.f;
        }
    };
    auto loadB = [&](int k0) {
        #pragma unroll
        for (int e = 0; e < B_EL; e++) {
            int i = tid + e * 256;
            if (!TRANSB) {
                int k = i / BNT, n = i % BNT;
                int gk = k0 + k, gn = n0 + n;
                rb[e] = (gk < K && gn < N) ? Bm[(long long)gk * ldb + gn] : 0.f;
            } else {
                int n = i >> 4, k = i & 15;
                int gn = n0 + n, gk = k0 + k;
                rb[e] = (gn < N && gk < K) ? Bm[(long long)gn * ldb + gk] : 0.f;
            }
        }
    };
    auto stash = [&](int s) {   // store regs -> smem stage s, tf32-rounded
        float* As = smem + s * STAGE;
        float* Bs = As + BM * LDA;
        #pragma unroll
        for (int e = 0; e < A_EL; e++) {
            int i = tid + e * 256;
            int m = i >> 4, k = i & 15;
            As[m * LDA + k] = wmma::__float_to_tf32(ra[e]);
        }
        #pragma unroll
        for (int e = 0; e < B_EL; e++) {
            int i = tid + e * 256;
            int k, n;
            if (!TRANSB) { k = i / BNT; n = i % BNT; }
            else         { n = i >> 4;  k = i & 15; }
            Bs[k * LDB + n] = wmma::__float_to_tf32(rb[e]);
        }
    };
    auto compute = [&](int s) {
        const float* As = smem + s * STAGE;
        const float* Bs = As + BM * LDA;
        #pragma unroll
        for (int ks = 0; ks < BK / 8; ks++) {
            wmma::fragment<wmma::matrix_a, 16, 16, 8, wmma::precision::tf32,
                           wmma::row_major> af[AF];
            wmma::fragment<wmma::matrix_b, 16, 16, 8, wmma::precision::tf32,
                           wmma::row_major> bf[BF];
            #pragma unroll
            for (int i = 0; i < AF; i++)
                wmma::load_matrix_sync(
                    af[i], As + (wm * WARP_M + i * 16) * LDA + ks * 8, LDA);
            #pragma unroll
            for (int j = 0; j < BF; j++)
                wmma::load_matrix_sync(
                    bf[j], Bs + (ks * 8) * LDB + wn * WARP_N + j * 16, LDB);
            #pragma unroll
            for (int i = 0; i < AF; i++)
                #pragma unroll
                for (int j = 0; j < BF; j++)
                    wmma::mma_sync(acc[i][j], af[i], bf[j], acc[i][j]);
        }
    };

    // ---- mainloop: 2-stage ping-pong, register prefetch ----
    int nk = (K + BK - 1) / BK;
    loadA(0); loadB(0);
    stash(0);
    __syncthreads();
    int cur = 0;
    for (int t = 1; t < nk; t++) {
        loadA(t * BK); loadB(t * BK);
        compute(cur);
        stash(cur ^ 1);
        __syncthreads();
        cur ^= 1;
    }
    compute(cur);
    __syncthreads();

    // ---- epilogue: stage 64-wide column halves through smem ----
    constexpr int NHALF = (BNT == 128) ? 2 : 1;
    #pragma unroll
    for (int h = 0; h < NHALF; h++) {
        bool mywarp = (BNT == 128) ? ((wn >> 1) == h) : true;
        if (mywarp) {
            int cbase = (BNT == 128) ? (wn & 1) * 32 : wn * 32;
            #pragma unroll
            for (int i = 0; i < AF; i++)
                #pragma unroll
                for (int j = 0; j < BF; j++)
                    wmma::store_matrix_sync(
                        smem + (wm * WARP_M + i * 16) * LDST + cbase + j * 16,
                        acc[i][j], LDST, wmma::mem_row_major);
        }
        __syncthreads();

        int nl = tid & 63;
        int n = n0 + h * 64 + nl;
        if (n < N) {
            float bn_ = (EPI == 1 || EPI == 3) ? bias[n] : 0.f;
            #pragma unroll 8
            for (int p = 0; p < 32; p++) {
                int r = (tid >> 6) + p * 4;
                int m = m0 + r;
                if (m >= M) break;
                float v = smem[r * LDST + nl] * alpha;
                if (EPI == 1) {
                    v += bn_;
                    v = 0.5f * v * (1.f + erff(v * 0.70710678118654752f));
                } else if (EPI == 2) {
                    v += Dp[(long long)m * ldc + n];
                } else if (EPI == 3) {
                    v += bn_ + Dp[(long long)m * ldc + n];
                }
                Cm[(long long)m * ldc + n] = v;
            }
        }
        if (h + 1 < NHALF) __syncthreads();
    }
}

// ---------------- classifier + final softmax: one block per batch ------------
__global__ void classifier_kernel(const float* __restrict__ hbuf,
                                  const float* __restrict__ Wc,
                                  const float* __restrict__ bc,
                                  float* __restrict__ out) {
    int b = blockIdx.x;
    int tid = threadIdx.x;  // 256
    __shared__ float xs[EE];
    __shared__ float lg[CC];
    __shared__ float red[256];

    const float* xr = hbuf + (long long)b * SS * EE;  // row s=0
    for (int i = tid; i < EE; i += 256) xs[i] = xr[i];
    __syncthreads();

    for (int c = tid; c < CC; c += 256) {
        float acc = bc[c];
        for (int e = 0; e < EE; e++) acc += xs[e] * Wc[(long long)e * CC + c];
        lg[c] = acc;
    }
    __syncthreads();

    float m = -1e30f;
    for (int c = tid; c < CC; c += 256) m = fmaxf(m, lg[c]);
    red[tid] = m; __syncthreads();
    for (int st = 128; st > 0; st >>= 1) {
        if (tid < st) red[tid] = fmaxf(red[tid], red[tid + st]);
        __syncthreads();
    }
    m = red[0];
    __syncthreads();

    float sum = 0.f;
    for (int c = tid; c < CC; c += 256) {
        float e = expf(lg[c] - m);
        lg[c] = e; sum += e;
    }
    red[tid] = sum; __syncthreads();
    for (int st = 128; st > 0; st >>= 1) {
        if (tid < st) red[tid] += red[tid + st];
        __syncthreads();
    }
    float inv = 1.f / red[0];
    for (int c = tid; c < CC; c += 256)
        out[(long long)b * CC + c] = lg[c] * inv;
}

// ---------------- host orchestration ----------------------------------------
extern "C" void kernel_launch(void* const* d_in, const int* in_sizes, int n_in,
                              void* d_out, int out_size) {
    const float* x     = (const float*)d_in[0];
    const float* Wk    = (const float*)d_in[1];
    const float* Wq    = (const float*)d_in[2];
    const float* Wv    = (const float*)d_in[3];
    const float* Wconv = (const float*)d_in[4];
    const float* ln1_w = (const float*)d_in[5];
    const float* ln1_b = (const float*)d_in[6];
    const float* ln2_w = (const float*)d_in[7];
    const float* ln2_b = (const float*)d_in[8];
    const float* W1    = (const float*)d_in[9];
    const float* b1    = (const float*)d_in[10];
    const float* W2    = (const float*)d_in[11];
    const float* b2    = (const float*)d_in[12];
    const float* Wc    = (const float*)d_in[13];
    const float* bc    = (const float*)d_in[14];
    float* out = (float*)d_out;

    float *ph, *pxn, *pq, *pk, *pv, *patt, *po, *pres1, *pff;
    cudaGetSymbolAddress((void**)&ph,    g_h);
    cudaGetSymbolAddress((void**)&pxn,   g_xn);
    cudaGetSymbolAddress((void**)&pq,    g_q);
    cudaGetSymbolAddress((void**)&pk,    g_k);
    cudaGetSymbolAddress((void**)&pv,    g_v);
    cudaGetSymbolAddress((void**)&patt,  g_att);
    cudaGetSymbolAddress((void**)&po,    g_o);
    cudaGetSymbolAddress((void**)&pres1, g_res1);
    cudaGetSymbolAddress((void**)&pff,   g_ff);

    cudaMemcpyAsync(ph, x, sizeof(float) * (size_t)BS * EE,
                    cudaMemcpyDeviceToDevice);

    const float inv_scale = 1.f / sqrtf((float)SS);
    const int MT = (BS + 127) / 128;  // 50 row tiles

    for (int l = 0; l < LL; l++) {
        const float* Wq_l = Wq + (long long)l * HH * EE * DHH;
        const float* Wk_l = Wk + (long long)l * HH * EE * DHH;
        const float* Wv_l = Wv + (long long)l * HH * EE * DHH;
        const float* Wcv_l = Wconv + (long long)l * EE * EE;
        const float* W1_l = W1 + (long long)l * EE * FF_;
        const float* b1_l = b1 + (long long)l * FF_;
        const float* W2_l = W2 + (long long)l * FF_ * EE;
        const float* b2_l = b2 + (long long)l * EE;

        // LN1
        layernorm_kernel<<<BS, 256>>>(ph, ln1_w + l * EE, ln1_b + l * EE, pxn);

        // Q,K,V: per-head GEMM  [BS x 768] @ [768 x 64]  (z over heads)
        {
            dim3 g(1, MT, HH);
            tc_gemm_kernel<0, false, 64><<<g, 256>>>(pxn, Wq_l, pq, nullptr, nullptr,
                BS, DHH, EE, EE, DHH, DHH,
                0, 0, 0, (long long)EE * DHH,
                0, (long long)BS * DHH, HH, 1.f);
            tc_gemm_kernel<0, false, 64><<<g, 256>>>(pxn, Wk_l, pk, nullptr, nullptr,
                BS, DHH, EE, EE, DHH, DHH,
                0, 0, 0, (long long)EE * DHH,
                0, (long long)BS * DHH, HH, 1.f);
            tc_gemm_kernel<0, false, 64><<<g, 256>>>(pxn, Wv_l, pv, nullptr, nullptr,
                BS, DHH, EE, EE, DHH, DHH,
                0, 0, 0, (long long)EE * DHH,
                0, (long long)BS * DHH, HH, 1.f);
        }

        // scores = Q @ K^T * inv_scale   (batched over b,h)
        {
            dim3 g((SS + 63) / 64, (SS + 127) / 128, BB * HH);
            tc_gemm_kernel<0, true, 64><<<g, 256>>>(pq, pk, patt, nullptr, nullptr,
                SS, SS, DHH, DHH, DHH, SS,
                (long long)SS * DHH, (long long)BS * DHH,
                (long long)SS * DHH, (long long)BS * DHH,
                (long long)HH * SS * SS, (long long)SS * SS, HH, inv_scale);
        }

        // softmax over last dim
        att_softmax_kernel<<<BB * HH * SS, 128>>>(patt);

        // O = att @ V  (write directly into concat-head layout [bs][h*64+d])
        {
            dim3 g(1, (SS + 127) / 128, BB * HH);
            tc_gemm_kernel<0, false, 64><<<g, 256>>>(patt, pv, po, nullptr, nullptr,
                SS, DHH, SS, SS, DHH, EE,
                (long long)HH * SS * SS, (long long)SS * SS,
                (long long)SS * DHH, (long long)BS * DHH,
                (long long)SS * EE, (long long)DHH, HH, 1.f);
        }

        // res1 = O @ Wconv + h
        {
            dim3 g(EE / 128, MT, 1);
            tc_gemm_kernel<2, false, 128><<<g, 256>>>(po, Wcv_l, pres1, nullptr, ph,
                BS, EE, EE, EE, EE, EE,
                0, 0, 0, 0, 0, 0, 1, 1.f);
        }

        // LN2
        layernorm_kernel<<<BS, 256>>>(pres1, ln2_w + l * EE, ln2_b + l * EE, pxn);

        // FF1 = gelu(xn2 @ W1 + b1)
        {
            dim3 g(FF_ / 128, MT, 1);
            tc_gemm_kernel<1, false, 128><<<g, 256>>>(pxn, W1_l, pff, b1_l, nullptr,
                BS, FF_, EE, EE, FF_, FF_,
                0, 0, 0, 0, 0, 0, 1, 1.f);
        }

        // h = FF1 @ W2 + b2 + res1
        {
            dim3 g(EE / 128, MT, 1);
            tc_gemm_kernel<3, false, 128><<<g, 256>>>(pff, W2_l, ph, b2_l, pres1,
                BS, EE, FF_, FF_, EE, EE,
                0, 0, 0, 0, 0, 0, 1, 1.f);
        }
    }

    // classifier + softmax
    classifier_kernel<<<BB, 256>>>(ph, Wc, bc, out);
}

// round 6
// speedup vs baseline: 2.6207x; 2.6207x over previous
#include <cuda_runtime.h>
#include <cuda_fp16.h>
#include <mma.h>
#include <math.h>

using namespace nvcuda;

// ---------------- problem constants ----------------
#define BB 32
#define SS 197
#define EE 768
#define HH 12
#define DHH 64
#define FF_ 2048
#define LL 4
#define CC 1000
#define BS (BB * SS)   // 6304
#define LN_EPS 1e-5f

// ---------------- scratch (device globals; allocation-free rule) ------------
__device__ float g_h   [BS * EE];
__device__ float g_xn  [BS * EE];
__device__ float g_q   [HH * BS * DHH];
__device__ float g_k   [HH * BS * DHH];
__device__ float g_v   [HH * BS * DHH];
__device__ float g_att [BB * HH * SS * SS];
__device__ float g_o   [BS * EE];
__device__ float g_res1[BS * EE];
__device__ float g_ff  [BS * FF_];

// ---------------- layernorm: one block per row (E=768) ----------------------
__global__ void layernorm_kernel(const float* __restrict__ x,
                                 const float* __restrict__ w,
                                 const float* __restrict__ b,
                                 float* __restrict__ out) {
    int row = blockIdx.x;
    const float* xr = x + (long long)row * EE;
    float* orow = out + (long long)row * EE;
    int tid = threadIdx.x;  // 256

    float s = 0.f, s2 = 0.f;
    #pragma unroll
    for (int i = tid; i < EE; i += 256) {
        float v = xr[i];
        s += v; s2 += v * v;
    }
    __shared__ float rs[256], rs2[256];
    rs[tid] = s; rs2[tid] = s2;
    __syncthreads();
    for (int st = 128; st > 0; st >>= 1) {
        if (tid < st) { rs[tid] += rs[tid + st]; rs2[tid] += rs2[tid + st]; }
        __syncthreads();
    }
    float mu = rs[0] * (1.f / EE);
    float var = rs2[0] * (1.f / EE) - mu * mu;
    float rstd = rsqrtf(var + LN_EPS);
    #pragma unroll
    for (int i = tid; i < EE; i += 256) {
        orow[i] = (xr[i] - mu) * rstd * w[i] + b[i];
    }
}

// ---------------- attention softmax: one block per row (len 197) -------------
__global__ void att_softmax_kernel(float* __restrict__ att) {
    long long row = blockIdx.x;
    float* r = att + row * (long long)SS;
    int tid = threadIdx.x;  // 128
    __shared__ float red[128];

    float m = -1e30f;
    for (int i = tid; i < SS; i += 128) m = fmaxf(m, r[i]);
    red[tid] = m; __syncthreads();
    for (int st = 64; st > 0; st >>= 1) {
        if (tid < st) red[tid] = fmaxf(red[tid], red[tid + st]);
        __syncthreads();
    }
    m = red[0];
    __syncthreads();

    float sum = 0.f;
    for (int i = tid; i < SS; i += 128) {
        float e = expf(r[i] - m);
        r[i] = e; sum += e;
    }
    red[tid] = sum; __syncthreads();
    for (int st = 64; st > 0; st >>= 1) {
        if (tid < st) red[tid] += red[tid + st];
        __syncthreads();
    }
    float inv = 1.f / red[0];
    for (int i = tid; i < SS; i += 128) r[i] *= inv;
}

// ---------------- FP16 TC GEMM (fp32 accum): 128xBNT tile, BK=32 ------------
// fp32 -> fp16 conversion happens once at smem staging; inner loop is pure
// LDSM + HMMA (m16n16k16). Single-buffered (round-3 proven sync structure).
// fp16 mantissa (10 bits) == tf32 mantissa, fp32 accumulate -> same error
// class as tf32 (~1.5e-4 observed).
// EPI: 0: C=alpha*acc  1: C=gelu(acc+bias)  2: C=acc+D  3: C=acc+bias+D
// TRANSB: logical B[k][n] stored as Bg[n][k] (A @ B^T).
template <int EPI, bool TRANSB, int BNT>
__global__ __launch_bounds__(256)
void tc_gemm_kernel(const float* __restrict__ A, const float* __restrict__ Bm,
                    float* __restrict__ Cm,
                    const float* __restrict__ bias, const float* __restrict__ Dm,
                    int M, int N, int K, int lda, int ldb, int ldc,
                    long long sA1, long long sA2, long long sB1, long long sB2,
                    long long sC1, long long sC2, int innerB, float alpha) {
    constexpr int BM = 128, BK = 32;
    constexpr int WCOLS  = (BNT == 128) ? 4 : 2;    // warps along n
    constexpr int WARP_M = (BNT == 128) ? 64 : 32;  // warp tile m
    constexpr int WARP_N = 32;
    constexpr int AF = WARP_M / 16;                 // 4 or 2
    constexpr int BF = WARP_N / 16;                 // 2
    constexpr int LDA_H = BK + 8;                   // 40 halfs (80B, mult 16B)
    constexpr int LDB_H = BNT + 8;                  // 136 / 72 halfs
    constexpr int LDST = 68;                        // epilogue staging (floats)
    // smem: staging (halfs) unioned with epilogue (floats)
    constexpr int STAGE_HALFS = BM * LDA_H + BK * LDB_H;
    constexpr int EPI_FLOATS  = BM * LDST;          // 8704
    constexpr int SMEM_BYTES =
        (STAGE_HALFS * 2 > EPI_FLOATS * 4) ? STAGE_HALFS * 2 : EPI_FLOATS * 4;

    int zo = blockIdx.z / innerB, zi = blockIdx.z % innerB;
    A  += zo * sA1 + zi * sA2;
    Bm += zo * sB1 + zi * sB2;
    long long coff = zo * sC1 + zi * sC2;
    Cm += coff;
    const float* Dp = (EPI == 2 || EPI == 3) ? (Dm + coff) : nullptr;

    const int m0 = blockIdx.y * BM, n0 = blockIdx.x * BNT;

    __shared__ __align__(16) char smem_raw[SMEM_BYTES];
    __half* As = reinterpret_cast<__half*>(smem_raw);
    __half* Bs = As + BM * LDA_H;
    float*  epi = reinterpret_cast<float*>(smem_raw);

    int tid = threadIdx.x;
    int wid = tid >> 5;
    int wm = wid % (8 / WCOLS);
    int wn = wid / (8 / WCOLS);

    wmma::fragment<wmma::accumulator, 16, 16, 16, float> acc[AF][BF];
    #pragma unroll
    for (int i = 0; i < AF; i++)
        #pragma unroll
        for (int j = 0; j < BF; j++)
            wmma::fill_fragment(acc[i][j], 0.f);

    for (int k0 = 0; k0 < K; k0 += BK) {
        // ---- stage A: BM x BK, half2-packed, coalesced along k ----
        #pragma unroll
        for (int e = 0; e < (BM * BK / 2) / 256; e++) {   // 8 iters
            int i2 = tid + e * 256;
            int m = i2 >> 4, kp = i2 & 15;
            int k = kp * 2;
            int gm = m0 + m, gk = k0 + k;
            float v0 = (gm < M && gk < K)     ? A[(long long)gm * lda + gk]     : 0.f;
            float v1 = (gm < M && gk + 1 < K) ? A[(long long)gm * lda + gk + 1] : 0.f;
            *reinterpret_cast<__half2*>(&As[m * LDA_H + k]) =
                __floats2half2_rn(v0, v1);
        }
        // ---- stage B: BK x BNT ----
        if (!TRANSB) {
            #pragma unroll
            for (int e = 0; e < (BK * BNT / 2) / 256; e++) {
                int i2 = tid + e * 256;
                int k = i2 / (BNT / 2);
                int n = (i2 % (BNT / 2)) * 2;
                int gk = k0 + k, gn = n0 + n;
                float v0 = (gk < K && gn < N)     ? Bm[(long long)gk * ldb + gn]     : 0.f;
                float v1 = (gk < K && gn + 1 < N) ? Bm[(long long)gk * ldb + gn + 1] : 0.f;
                *reinterpret_cast<__half2*>(&Bs[k * LDB_H + n]) =
                    __floats2half2_rn(v0, v1);
            }
        } else {
            #pragma unroll
            for (int e = 0; e < (BK * BNT) / 256; e++) {
                int i = tid + e * 256;
                int n = i >> 5, k = i & 31;
                int gn = n0 + n, gk = k0 + k;
                float v = (gn < N && gk < K) ? Bm[(long long)gn * ldb + gk] : 0.f;
                Bs[k * LDB_H + n] = __float2half_rn(v);
            }
        }
        __syncthreads();

        // ---- MMA: 2 k16 steps ----
        #pragma unroll
        for (int kt = 0; kt < BK / 16; kt++) {
            wmma::fragment<wmma::matrix_a, 16, 16, 16, __half,
                           wmma::row_major> af[AF];
            wmma::fragment<wmma::matrix_b, 16, 16, 16, __half,
                           wmma::row_major> bf[BF];
            #pragma unroll
            for (int i = 0; i < AF; i++)
                wmma::load_matrix_sync(
                    af[i], As + (wm * WARP_M + i * 16) * LDA_H + kt * 16, LDA_H);
            #pragma unroll
            for (int j = 0; j < BF; j++)
                wmma::load_matrix_sync(
                    bf[j], Bs + (kt * 16) * LDB_H + wn * WARP_N + j * 16, LDB_H);
            #pragma unroll
            for (int i = 0; i < AF; i++)
                #pragma unroll
                for (int j = 0; j < BF; j++)
                    wmma::mma_sync(acc[i][j], af[i], bf[j], acc[i][j]);
        }
        __syncthreads();
    }

    // ---- epilogue: stage 64-wide column halves through smem (fp32) ----
    constexpr int NHALF = (BNT == 128) ? 2 : 1;
    #pragma unroll
    for (int h = 0; h < NHALF; h++) {
        bool mywarp = (BNT == 128) ? ((wn >> 1) == h) : true;
        if (mywarp) {
            int cbase = (BNT == 128) ? (wn & 1) * 32 : wn * 32;
            #pragma unroll
            for (int i = 0; i < AF; i++)
                #pragma unroll
                for (int j = 0; j < BF; j++)
                    wmma::store_matrix_sync(
                        epi + (wm * WARP_M + i * 16) * LDST + cbase + j * 16,
                        acc[i][j], LDST, wmma::mem_row_major);
        }
        __syncthreads();

        int nl = tid & 63;
        int n = n0 + h * 64 + nl;
        if (n < N) {
            float bn_ = (EPI == 1 || EPI == 3) ? bias[n] : 0.f;
            #pragma unroll 8
            for (int p = 0; p < 32; p++) {
                int r = (tid >> 6) + p * 4;
                int m = m0 + r;
                if (m >= M) break;
                float v = epi[r * LDST + nl] * alpha;
                if (EPI == 1) {
                    v += bn_;
                    v = 0.5f * v * (1.f + erff(v * 0.70710678118654752f));
                } else if (EPI == 2) {
                    v += Dp[(long long)m * ldc + n];
                } else if (EPI == 3) {
                    v += bn_ + Dp[(long long)m * ldc + n];
                }
                Cm[(long long)m * ldc + n] = v;
            }
        }
        if (h + 1 < NHALF) __syncthreads();
    }
}

// ---------------- classifier + final softmax: one block per batch ------------
__global__ void classifier_kernel(const float* __restrict__ hbuf,
                                  const float* __restrict__ Wc,
                                  const float* __restrict__ bc,
                                  float* __restrict__ out) {
    int b = blockIdx.x;
    int tid = threadIdx.x;  // 256
    __shared__ float xs[EE];
    __shared__ float lg[CC];
    __shared__ float red[256];

    const float* xr = hbuf + (long long)b * SS * EE;  // row s=0
    for (int i = tid; i < EE; i += 256) xs[i] = xr[i];
    __syncthreads();

    for (int c = tid; c < CC; c += 256) {
        float acc = bc[c];
        for (int e = 0; e < EE; e++) acc += xs[e] * Wc[(long long)e * CC + c];
        lg[c] = acc;
    }
    __syncthreads();

    float m = -1e30f;
    for (int c = tid; c < CC; c += 256) m = fmaxf(m, lg[c]);
    red[tid] = m; __syncthreads();
    for (int st = 128; st > 0; st >>= 1) {
        if (tid < st) red[tid] = fmaxf(red[tid], red[tid + st]);
        __syncthreads();
    }
    m = red[0];
    __syncthreads();

    float sum = 0.f;
    for (int c = tid; c < CC; c += 256) {
        float e = expf(lg[c] - m);
        lg[c] = e; sum += e;
    }
    red[tid] = sum; __syncthreads();
    for (int st = 128; st > 0; st >>= 1) {
        if (tid < st) red[tid] += red[tid + st];
        __syncthreads();
    }
    float inv = 1.f / red[0];
    for (int c = tid; c < CC; c += 256)
        out[(long long)b * CC + c] = lg[c] * inv;
}

// ---------------- host orchestration ----------------------------------------
extern "C" void kernel_launch(void* const* d_in, const int* in_sizes, int n_in,
                              void* d_out, int out_size) {
    const float* x     = (const float*)d_in[0];
    const float* Wk    = (const float*)d_in[1];
    const float* Wq    = (const float*)d_in[2];
    const float* Wv    = (const float*)d_in[3];
    const float* Wconv = (const float*)d_in[4];
    const float* ln1_w = (const float*)d_in[5];
    const float* ln1_b = (const float*)d_in[6];
    const float* ln2_w = (const float*)d_in[7];
    const float* ln2_b = (const float*)d_in[8];
    const float* W1    = (const float*)d_in[9];
    const float* b1    = (const float*)d_in[10];
    const float* W2    = (const float*)d_in[11];
    const float* b2    = (const float*)d_in[12];
    const float* Wc    = (const float*)d_in[13];
    const float* bc    = (const float*)d_in[14];
    float* out = (float*)d_out;

    float *ph, *pxn, *pq, *pk, *pv, *patt, *po, *pres1, *pff;
    cudaGetSymbolAddress((void**)&ph,    g_h);
    cudaGetSymbolAddress((void**)&pxn,   g_xn);
    cudaGetSymbolAddress((void**)&pq,    g_q);
    cudaGetSymbolAddress((void**)&pk,    g_k);
    cudaGetSymbolAddress((void**)&pv,    g_v);
    cudaGetSymbolAddress((void**)&patt,  g_att);
    cudaGetSymbolAddress((void**)&po,    g_o);
    cudaGetSymbolAddress((void**)&pres1, g_res1);
    cudaGetSymbolAddress((void**)&pff,   g_ff);

    cudaMemcpyAsync(ph, x, sizeof(float) * (size_t)BS * EE,
                    cudaMemcpyDeviceToDevice);

    const float inv_scale = 1.f / sqrtf((float)SS);
    const int MT = (BS + 127) / 128;  // 50 row tiles

    for (int l = 0; l < LL; l++) {
        const float* Wq_l = Wq + (long long)l * HH * EE * DHH;
        const float* Wk_l = Wk + (long long)l * HH * EE * DHH;
        const float* Wv_l = Wv + (long long)l * HH * EE * DHH;
        const float* Wcv_l = Wconv + (long long)l * EE * EE;
        const float* W1_l = W1 + (long long)l * EE * FF_;
        const float* b1_l = b1 + (long long)l * FF_;
        const float* W2_l = W2 + (long long)l * FF_ * EE;
        const float* b2_l = b2 + (long long)l * EE;

        // LN1
        layernorm_kernel<<<BS, 256>>>(ph, ln1_w + l * EE, ln1_b + l * EE, pxn);

        // Q,K,V: per-head GEMM  [BS x 768] @ [768 x 64]  (z over heads)
        {
            dim3 g(1, MT, HH);
            tc_gemm_kernel<0, false, 64><<<g, 256>>>(pxn, Wq_l, pq, nullptr, nullptr,
                BS, DHH, EE, EE, DHH, DHH,
                0, 0, 0, (long long)EE * DHH,
                0, (long long)BS * DHH, HH, 1.f);
            tc_gemm_kernel<0, false, 64><<<g, 256>>>(pxn, Wk_l, pk, nullptr, nullptr,
                BS, DHH, EE, EE, DHH, DHH,
                0, 0, 0, (long long)EE * DHH,
                0, (long long)BS * DHH, HH, 1.f);
            tc_gemm_kernel<0, false, 64><<<g, 256>>>(pxn, Wv_l, pv, nullptr, nullptr,
                BS, DHH, EE, EE, DHH, DHH,
                0, 0, 0, (long long)EE * DHH,
                0, (long long)BS * DHH, HH, 1.f);
        }

        // scores = Q @ K^T * inv_scale   (batched over b,h)
        {
            dim3 g((SS + 63) / 64, (SS + 127) / 128, BB * HH);
            tc_gemm_kernel<0, true, 64><<<g, 256>>>(pq, pk, patt, nullptr, nullptr,
                SS, SS, DHH, DHH, DHH, SS,
                (long long)SS * DHH, (long long)BS * DHH,
                (long long)SS * DHH, (long long)BS * DHH,
                (long long)HH * SS * SS, (long long)SS * SS, HH, inv_scale);
        }

        // softmax over last dim
        att_softmax_kernel<<<BB * HH * SS, 128>>>(patt);

        // O = att @ V  (write directly into concat-head layout [bs][h*64+d])
        {
            dim3 g(1, (SS + 127) / 128, BB * HH);
            tc_gemm_kernel<0, false, 64><<<g, 256>>>(patt, pv, po, nullptr, nullptr,
                SS, DHH, SS, SS, DHH, EE,
                (long long)HH * SS * SS, (long long)SS * SS,
                (long long)SS * DHH, (long long)BS * DHH,
                (long long)SS * EE, (long long)DHH, HH, 1.f);
        }

        // res1 = O @ Wconv + h
        {
            dim3 g(EE / 128, MT, 1);
            tc_gemm_kernel<2, false, 128><<<g, 256>>>(po, Wcv_l, pres1, nullptr, ph,
                BS, EE, EE, EE, EE, EE,
                0, 0, 0, 0, 0, 0, 1, 1.f);
        }

        // LN2
        layernorm_kernel<<<BS, 256>>>(pres1, ln2_w + l * EE, ln2_b + l * EE, pxn);

        // FF1 = gelu(xn2 @ W1 + b1)
        {
            dim3 g(FF_ / 128, MT, 1);
            tc_gemm_kernel<1, false, 128><<<g, 256>>>(pxn, W1_l, pff, b1_l, nullptr,
                BS, FF_, EE, EE, FF_, FF_,
                0, 0, 0, 0, 0, 0, 1, 1.f);
        }

        // h = FF1 @ W2 + b2 + res1
        {
            dim3 g(EE / 128, MT, 1);
            tc_gemm_kernel<3, false, 128><<<g, 256>>>(pff, W2_l, ph, b2_l, pres1,
                BS, EE, FF_, FF_, EE, EE,
                0, 0, 0, 0, 0, 0, 1, 1.f);
        }
    }

    // classifier + softmax
    classifier_kernel<<<BB, 256>>>(ph, Wc, bc, out);
}

// round 7
// speedup vs baseline: 3.5881x; 1.3692x over previous
#include <cuda_runtime.h>
#include <cuda_fp16.h>
#include <mma.h>
#include <math.h>

using namespace nvcuda;

// ---------------- problem constants ----------------
#define BB 32
#define SS 197
#define EE 768
#define HH 12
#define DHH 64
#define FF_ 2048
#define LL 4
#define CC 1000
#define BS (BB * SS)     // 6304
#define SP 224           // padded seq (mult of 32) for att buffers
#define NQKV 2304        // 3 * H * DH packed output width
#define LN_EPS 1e-5f

// ---------------- scratch (device globals; allocation-free rule) ------------
__device__ float  g_h    [BS * EE];
__device__ float  g_res1 [BS * EE];
__device__ float  g_att  [BB * HH * SS * SP];        // fp32 scores
__device__ __half g_xnh  [BS * EE];
__device__ __half g_qkvh [(BS + 32) * NQKV];         // [bs][mat*768+h*64+d], padded rows
__device__ __half g_attph[BB * HH * SS * SP];        // half probs, k-padded w/ zeros
__device__ __half g_oh   [BS * EE];
__device__ __half g_ffh  [BS * FF_];
// fp16 weights (converted once per launch)
__device__ __half g_wqkv [LL * EE * NQKV];           // [l][e][mat*768+h*64+d]
__device__ __half g_wcv  [LL * EE * EE];
__device__ __half g_w1   [LL * EE * FF_];
__device__ __half g_w2   [LL * FF_ * EE];

// ---------------- weight conversion / packing -------------------------------
__global__ void cvt_f2h_kernel(const float* __restrict__ src,
                               __half* __restrict__ dst, int n) {
    int i = blockIdx.x * 256 + threadIdx.x;
    if (i < n) dst[i] = __float2half_rn(src[i]);
}

__global__ void pack_qkv_kernel(const float* __restrict__ Wq,
                                const float* __restrict__ Wk,
                                const float* __restrict__ Wv,
                                __half* __restrict__ dst) {
    const int per = LL * HH * EE * DHH;          // 2359296
    int i = blockIdx.x * 256 + threadIdx.x;
    if (i >= 3 * per) return;
    int mat = i / per, r = i % per;
    int d = r % DHH;
    int e = (r / DHH) % EE;
    int h = (r / (DHH * EE)) % HH;
    int l = r / (DHH * EE * HH);
    const float* src = (mat == 0) ? Wq : (mat == 1) ? Wk : Wv;
    dst[((long long)l * EE + e) * NQKV + mat * 768 + h * 64 + d] =
        __float2half_rn(src[r]);
}

// ---------------- layernorm: one block per row, fp16 out --------------------
__global__ void layernorm_kernel(const float* __restrict__ x,
                                 const float* __restrict__ w,
                                 const float* __restrict__ b,
                                 __half* __restrict__ out) {
    int row = blockIdx.x;
    const float* xr = x + (long long)row * EE;
    __half* orow = out + (long long)row * EE;
    int tid = threadIdx.x;  // 256

    float s = 0.f, s2 = 0.f;
    #pragma unroll
    for (int i = tid; i < EE; i += 256) {
        float v = xr[i];
        s += v; s2 += v * v;
    }
    __shared__ float rs[256], rs2[256];
    rs[tid] = s; rs2[tid] = s2;
    __syncthreads();
    for (int st = 128; st > 0; st >>= 1) {
        if (tid < st) { rs[tid] += rs[tid + st]; rs2[tid] += rs2[tid + st]; }
        __syncthreads();
    }
    float mu = rs[0] * (1.f / EE);
    float var = rs2[0] * (1.f / EE) - mu * mu;
    float rstd = rsqrtf(var + LN_EPS);
    #pragma unroll
    for (int i = tid; i < EE; i += 256) {
        orow[i] = __float2half_rn((xr[i] - mu) * rstd * w[i] + b[i]);
    }
}

// ---------------- attention softmax: fp32 in, half out (zero k-pad) ---------
__global__ void att_softmax_kernel(const float* __restrict__ att,
                                   __half* __restrict__ attp) {
    long long row = blockIdx.x;
    const float* r = att + row * SP;
    __half* o = attp + row * SP;
    int tid = threadIdx.x;  // 128
    __shared__ float red[128];
    __shared__ float ex[SS];

    float m = -1e30f;
    for (int i = tid; i < SS; i += 128) m = fmaxf(m, r[i]);
    red[tid] = m; __syncthreads();
    for (int st = 64; st > 0; st >>= 1) {
        if (tid < st) red[tid] = fmaxf(red[tid], red[tid + st]);
        __syncthreads();
    }
    m = red[0];
    __syncthreads();

    float sum = 0.f;
    for (int i = tid; i < SS; i += 128) {
        float e = expf(r[i] - m);
        ex[i] = e; sum += e;
    }
    red[tid] = sum; __syncthreads();
    for (int st = 64; st > 0; st >>= 1) {
        if (tid < st) red[tid] += red[tid + st];
        __syncthreads();
    }
    float inv = 1.f / red[0];
    for (int i = tid; i < SP; i += 128)
        o[i] = (i < SS) ? __float2half_rn(ex[i] * inv) : __half(0.f);
}

// ---------------- FP16-native TC GEMM (fp32 accum) --------------------------
// A, B are fp16 in gmem; staging is pure uint4 copy (no conversion).
// Requires K % 32 == 0 and lda/ldb % 8 == 0 (guaranteed by buffer padding).
// EPI: 0: C=alpha*acc  1: C=gelu(acc+bias)  2: C=acc+D  3: C=acc+bias+D
// OUTH: write fp16 output. TRANSB: B stored as Bg[n][k] (A @ B^T).
template <int EPI, bool TRANSB, int BNT, bool OUTH>
__global__ __launch_bounds__(256)
void hgemm_kernel(const __half* __restrict__ A, const __half* __restrict__ Bm,
                  void* __restrict__ Cv,
                  const float* __restrict__ bias, const float* __restrict__ Dm,
                  int M, int N, int K, int lda, int ldb, int ldc,
                  long long sA1, long long sA2, long long sB1, long long sB2,
                  long long sC1, long long sC2, int innerB, float alpha) {
    constexpr int BM = 128, BK = 32;
    constexpr int WCOLS  = (BNT == 128) ? 4 : 2;
    constexpr int WARP_M = (BNT == 128) ? 64 : 32;
    constexpr int WARP_N = 32;
    constexpr int AF = WARP_M / 16;
    constexpr int BF = WARP_N / 16;
    constexpr int LDA_H = BK + 8;    // 40
    constexpr int LDB_H = BNT + 8;   // 136 / 72
    constexpr int LDST = 68;
    constexpr int STAGE_HALFS = BM * LDA_H + BK * LDB_H;
    constexpr int EPI_BYTES = BM * LDST * 4;
    constexpr int SMEM_BYTES =
        (STAGE_HALFS * 2 > EPI_BYTES) ? STAGE_HALFS * 2 : EPI_BYTES;

    int zo = blockIdx.z / innerB, zi = blockIdx.z % innerB;
    A  += zo * sA1 + zi * sA2;
    Bm += zo * sB1 + zi * sB2;
    long long coff = zo * sC1 + zi * sC2;
    const float* Dp = (EPI == 2 || EPI == 3) ? (Dm + coff) : nullptr;

    const int m0 = blockIdx.y * BM, n0 = blockIdx.x * BNT;

    __shared__ __align__(16) char smem_raw[SMEM_BYTES];
    __half* As = reinterpret_cast<__half*>(smem_raw);
    __half* Bs = As + BM * LDA_H;
    float*  epi = reinterpret_cast<float*>(smem_raw);

    int tid = threadIdx.x;
    int wid = tid >> 5;
    int wm = wid % (8 / WCOLS);
    int wn = wid / (8 / WCOLS);

    wmma::fragment<wmma::accumulator, 16, 16, 16, float> acc[AF][BF];
    #pragma unroll
    for (int i = 0; i < AF; i++)
        #pragma unroll
        for (int j = 0; j < BF; j++)
            wmma::fill_fragment(acc[i][j], 0.f);

    const uint4 z4 = {0u, 0u, 0u, 0u};

    for (int k0 = 0; k0 < K; k0 += BK) {
        // ---- stage A: BM x BK, uint4 copy (8 halfs), only m predicated ----
        #pragma unroll
        for (int e = 0; e < (BM * BK / 8) / 256; e++) {   // 2 iters
            int i = tid + e * 256;
            int m = i >> 2, k = (i & 3) * 8;
            int gm = m0 + m;
            uint4 v = (gm < M)
                ? *reinterpret_cast<const uint4*>(A + (long long)gm * lda + k0 + k)
                : z4;
            *reinterpret_cast<uint4*>(&As[m * LDA_H + k]) = v;
        }
        // ---- stage B ----
        if (!TRANSB) {
            constexpr int VR = BNT / 8;                   // vecs per row
            #pragma unroll
            for (int e = 0; e < (BK * BNT / 8) / 256; e++) {
                int i = tid + e * 256;
                int k = i / VR, n = (i % VR) * 8;
                int gn = n0 + n;
                uint4 v = (gn + 8 <= N)
                    ? *reinterpret_cast<const uint4*>(
                          Bm + (long long)(k0 + k) * ldb + gn)
                    : z4;
                if (gn + 8 > N && gn < N) {               // ragged edge
                    __half tmp[8];
                    #pragma unroll
                    for (int j = 0; j < 8; j++)
                        tmp[j] = (gn + j < N)
                            ? Bm[(long long)(k0 + k) * ldb + gn + j]
                            : __half(0.f);
                    v = *reinterpret_cast<const uint4*>(tmp);
                }
                *reinterpret_cast<uint4*>(&Bs[k * LDB_H + n]) = v;
            }
        } else {
            // each thread: 8 k-halfs of one n-row, scattered smem stores
            #pragma unroll
            for (int e = 0; e < (BK * BNT / 8) / 256; e++) {
                int i = tid + e * 256;
                int n = i / (BK / 8), k = (i % (BK / 8)) * 8;
                int gn = n0 + n;
                uint4 v = (gn < N)
                    ? *reinterpret_cast<const uint4*>(
                          Bm + (long long)gn * ldb + k0 + k)
                    : z4;
                const __half* hv = reinterpret_cast<const __half*>(&v);
                #pragma unroll
                for (int j = 0; j < 8; j++)
                    Bs[(k + j) * LDB_H + n] = hv[j];
            }
        }
        __syncthreads();

        #pragma unroll
        for (int kt = 0; kt < BK / 16; kt++) {
            wmma::fragment<wmma::matrix_a, 16, 16, 16, __half,
                           wmma::row_major> af[AF];
            wmma::fragment<wmma::matrix_b, 16, 16, 16, __half,
                           wmma::row_major> bf[BF];
            #pragma unroll
            for (int i = 0; i < AF; i++)
                wmma::load_matrix_sync(
                    af[i], As + (wm * WARP_M + i * 16) * LDA_H + kt * 16, LDA_H);
            #pragma unroll
            for (int j = 0; j < BF; j++)
                wmma::load_matrix_sync(
                    bf[j], Bs + (kt * 16) * LDB_H + wn * WARP_N + j * 16, LDB_H);
            #pragma unroll
            for (int i = 0; i < AF; i++)
                #pragma unroll
                for (int j = 0; j < BF; j++)
                    wmma::mma_sync(acc[i][j], af[i], bf[j], acc[i][j]);
        }
        __syncthreads();
    }

    // ---- epilogue: stage 64-wide column halves through fp32 smem ----
    constexpr int NHALF = (BNT == 128) ? 2 : 1;
    #pragma unroll
    for (int h = 0; h < NHALF; h++) {
        bool mywarp = (BNT == 128) ? ((wn >> 1) == h) : true;
        if (mywarp) {
            int cbase = (BNT == 128) ? (wn & 1) * 32 : wn * 32;
            #pragma unroll
            for (int i = 0; i < AF; i++)
                #pragma unroll
                for (int j = 0; j < BF; j++)
                    wmma::store_matrix_sync(
                        epi + (wm * WARP_M + i * 16) * LDST + cbase + j * 16,
                        acc[i][j], LDST, wmma::mem_row_major);
        }
        __syncthreads();

        int nl = tid & 63;
        int n = n0 + h * 64 + nl;
        if (n < N) {
            float bn_ = (EPI == 1 || EPI == 3) ? bias[n] : 0.f;
            #pragma unroll 8
            for (int p = 0; p < 32; p++) {
                int r = (tid >> 6) + p * 4;
                int m = m0 + r;
                if (m >= M) break;
                float v = epi[r * LDST + nl] * alpha;
                if (EPI == 1) {
                    v += bn_;
                    v = 0.5f * v * (1.f + erff(v * 0.70710678118654752f));
                } else if (EPI == 2) {
                    v += Dp[(long long)m * ldc + n];
                } else if (EPI == 3) {
                    v += bn_ + Dp[(long long)m * ldc + n];
                }
                if (OUTH)
                    ((__half*)Cv)[coff + (long long)m * ldc + n] =
                        __float2half_rn(v);
                else
                    ((float*)Cv)[coff + (long long)m * ldc + n] = v;
            }
        }
        if (h + 1 < NHALF) __syncthreads();
    }
}

// ---------------- classifier + final softmax: one block per batch ------------
__global__ void classifier_kernel(const float* __restrict__ hbuf,
                                  const float* __restrict__ Wc,
                                  const float* __restrict__ bc,
                                  float* __restrict__ out) {
    int b = blockIdx.x;
    int tid = threadIdx.x;  // 256
    __shared__ float xs[EE];
    __shared__ float lg[CC];
    __shared__ float red[256];

    const float* xr = hbuf + (long long)b * SS * EE;  // row s=0
    for (int i = tid; i < EE; i += 256) xs[i] = xr[i];
    __syncthreads();

    for (int c = tid; c < CC; c += 256) {
        float acc = bc[c];
        for (int e = 0; e < EE; e++) acc += xs[e] * Wc[(long long)e * CC + c];
        lg[c] = acc;
    }
    __syncthreads();

    float m = -1e30f;
    for (int c = tid; c < CC; c += 256) m = fmaxf(m, lg[c]);
    red[tid] = m; __syncthreads();
    for (int st = 128; st > 0; st >>= 1) {
        if (tid < st) red[tid] = fmaxf(red[tid], red[tid + st]);
        __syncthreads();
    }
    m = red[0];
    __syncthreads();

    float sum = 0.f;
    for (int c = tid; c < CC; c += 256) {
        float e = expf(lg[c] - m);
        lg[c] = e; sum += e;
    }
    red[tid] = sum; __syncthreads();
    for (int st = 128; st > 0; st >>= 1) {
        if (tid < st) red[tid] += red[tid + st];
        __syncthreads();
    }
    float inv = 1.f / red[0];
    for (int c = tid; c < CC; c += 256)
        out[(long long)b * CC + c] = lg[c] * inv;
}

// ---------------- host orchestration ----------------------------------------
extern "C" void kernel_launch(void* const* d_in, const int* in_sizes, int n_in,
                              void* d_out, int out_size) {
    const float* x     = (const float*)d_in[0];
    const float* Wk    = (const float*)d_in[1];
    const float* Wq    = (const float*)d_in[2];
    const float* Wv    = (const float*)d_in[3];
    const float* Wconv = (const float*)d_in[4];
    const float* ln1_w = (const float*)d_in[5];
    const float* ln1_b = (const float*)d_in[6];
    const float* ln2_w = (const float*)d_in[7];
    const float* ln2_b = (const float*)d_in[8];
    const float* W1    = (const float*)d_in[9];
    const float* b1    = (const float*)d_in[10];
    const float* W2    = (const float*)d_in[11];
    const float* b2    = (const float*)d_in[12];
    const float* Wc    = (const float*)d_in[13];
    const float* bc    = (const float*)d_in[14];
    float* out = (float*)d_out;

    float *ph, *pres1, *patt;
    __half *pxnh, *pqkvh, *pattph, *poh, *pffh, *pwqkv, *pwcv, *pw1, *pw2;
    cudaGetSymbolAddress((void**)&ph,     g_h);
    cudaGetSymbolAddress((void**)&pres1,  g_res1);
    cudaGetSymbolAddress((void**)&patt,   g_att);
    cudaGetSymbolAddress((void**)&pxnh,   g_xnh);
    cudaGetSymbolAddress((void**)&pqkvh,  g_qkvh);
    cudaGetSymbolAddress((void**)&pattph, g_attph);
    cudaGetSymbolAddress((void**)&poh,    g_oh);
    cudaGetSymbolAddress((void**)&pffh,   g_ffh);
    cudaGetSymbolAddress((void**)&pwqkv,  g_wqkv);
    cudaGetSymbolAddress((void**)&pwcv,   g_wcv);
    cudaGetSymbolAddress((void**)&pw1,    g_w1);
    cudaGetSymbolAddress((void**)&pw2,    g_w2);

    cudaMemcpyAsync(ph, x, sizeof(float) * (size_t)BS * EE,
                    cudaMemcpyDeviceToDevice);

    // ---- weight conversion pre-pass (graph-captured, deterministic) ----
    {
        int nq = 3 * LL * HH * EE * DHH;
        pack_qkv_kernel<<<(nq + 255) / 256, 256>>>(Wq, Wk, Wv, pwqkv);
        int ncv = LL * EE * EE;
        cvt_f2h_kernel<<<(ncv + 255) / 256, 256>>>(Wconv, pwcv, ncv);
        int n1 = LL * EE * FF_;
        cvt_f2h_kernel<<<(n1 + 255) / 256, 256>>>(W1, pw1, n1);
        cvt_f2h_kernel<<<(n1 + 255) / 256, 256>>>(W2, pw2, n1);
    }

    const float inv_scale = 1.f / sqrtf((float)SS);
    const int MT = (BS + 127) / 128;  // 50 row tiles

    for (int l = 0; l < LL; l++) {
        const __half* wqkv_l = pwqkv + (long long)l * EE * NQKV;
        const __half* wcv_l  = pwcv + (long long)l * EE * EE;
        const __half* w1_l   = pw1 + (long long)l * EE * FF_;
        const __half* w2_l   = pw2 + (long long)l * FF_ * EE;
        const float* b1_l = b1 + (long long)l * FF_;
        const float* b2_l = b2 + (long long)l * EE;

        // LN1 -> half
        layernorm_kernel<<<BS, 256>>>(ph, ln1_w + l * EE, ln1_b + l * EE, pxnh);

        // packed QKV: [6304 x 768] @ [768 x 2304] -> half
        {
            dim3 g(NQKV / 128, MT, 1);
            hgemm_kernel<0, false, 128, true><<<g, 256>>>(
                pxnh, wqkv_l, pqkvh, nullptr, nullptr,
                BS, NQKV, EE, EE, NQKV, NQKV,
                0, 0, 0, 0, 0, 0, 1, 1.f);
        }

        // scores = Q @ K^T * inv_scale (batched over b,h; strided qkv views)
        {
            dim3 g((SS + 63) / 64, (SS + 127) / 128, BB * HH);
            hgemm_kernel<0, true, 64, false><<<g, 256>>>(
                pqkvh, pqkvh + 768, patt, nullptr, nullptr,
                SS, SS, DHH, NQKV, NQKV, SP,
                (long long)SS * NQKV, 64, (long long)SS * NQKV, 64,
                (long long)HH * SS * SP, (long long)SS * SP, HH, inv_scale);
        }

        // softmax -> half probs (k-padded to 224 with zeros)
        att_softmax_kernel<<<BB * HH * SS, 128>>>(patt, pattph);

        // O = probs @ V  (K=224 padded; V rows beyond BS are zero-initialized)
        {
            dim3 g(1, (SS + 127) / 128, BB * HH);
            hgemm_kernel<0, false, 64, true><<<g, 256>>>(
                pattph, pqkvh + 1536, poh, nullptr, nullptr,
                SS, DHH, SP, SP, NQKV, EE,
                (long long)HH * SS * SP, (long long)SS * SP,
                (long long)SS * NQKV, 64,
                (long long)SS * EE, (long long)DHH, HH, 1.f);
        }

        // res1 = O @ Wconv + h   (fp32 out)
        {
            dim3 g(EE / 128, MT, 1);
            hgemm_kernel<2, false, 128, false><<<g, 256>>>(
                poh, wcv_l, pres1, nullptr, ph,
                BS, EE, EE, EE, EE, EE,
                0, 0, 0, 0, 0, 0, 1, 1.f);
        }

        // LN2 -> half
        layernorm_kernel<<<BS, 256>>>(pres1, ln2_w + l * EE, ln2_b + l * EE,
                                      pxnh);

        // FF1 = gelu(xn2 @ W1 + b1) -> half
        {
            dim3 g(FF_ / 128, MT, 1);
            hgemm_kernel<1, false, 128, true><<<g, 256>>>(
                pxnh, w1_l, pffh, b1_l, nullptr,
                BS, FF_, EE, EE, FF_, FF_,
                0, 0, 0, 0, 0, 0, 1, 1.f);
        }

        // h = FF1 @ W2 + b2 + res1  (fp32 out)
        {
            dim3 g(EE / 128, MT, 1);
            hgemm_kernel<3, false, 128, false><<<g, 256>>>(
                pffh, w2_l, ph, b2_l, pres1,
                BS, EE, FF_, FF_, EE, EE,
                0, 0, 0, 0, 0, 0, 1, 1.f);
        }
    }

    // classifier + softmax
    classifier_kernel<<<BB, 256>>>(ph, Wc, bc, out);
}

// round 8
// speedup vs baseline: 4.2345x; 1.1801x over previous
#include <cuda_runtime.h>
#include <cuda_fp16.h>
#include <mma.h>
#include <math.h>

using namespace nvcuda;

// ---------------- problem constants ----------------
#define BB 32
#define SS 197
#define EE 768
#define HH 12
#define DHH 64
#define FF_ 2048
#define LL 4
#define CC 1000
#define BS (BB * SS)     // 6304
#define SP2 256          // padded key length inside fused attention
#define NQKV 2304        // 3 * H * DH packed output width
#define LN_EPS 1e-5f

// ---------------- scratch (device globals; allocation-free rule) ------------
__device__ float  g_h    [BS * EE];
__device__ float  g_res1 [BS * EE];
__device__ __half g_xnh  [BS * EE];
__device__ __half g_qkvh [(BS + 32) * NQKV];
__device__ __half g_oh   [BS * EE];
__device__ __half g_ffh  [BS * FF_];
// fp16 weights (converted once per launch)
__device__ __half g_wqkv [LL * EE * NQKV];
__device__ __half g_wcv  [LL * EE * EE];
__device__ __half g_w1   [LL * EE * FF_];
__device__ __half g_w2   [LL * FF_ * EE];

// ---------------- weight conversion (vectorized: 8 elems/thread) ------------
__global__ void cvt_f2h_kernel(const float* __restrict__ src,
                               __half* __restrict__ dst, int n8) {
    int i = blockIdx.x * 256 + threadIdx.x;
    if (i >= n8) return;
    long long o = (long long)i * 8;
    float4 v0 = *reinterpret_cast<const float4*>(src + o);
    float4 v1 = *reinterpret_cast<const float4*>(src + o + 4);
    __half2 h[4];
    h[0] = __floats2half2_rn(v0.x, v0.y);
    h[1] = __floats2half2_rn(v0.z, v0.w);
    h[2] = __floats2half2_rn(v1.x, v1.y);
    h[3] = __floats2half2_rn(v1.z, v1.w);
    *reinterpret_cast<uint4*>(dst + o) = *reinterpret_cast<uint4*>(h);
}

__global__ void pack_qkv_kernel(const float* __restrict__ Wq,
                                const float* __restrict__ Wk,
                                const float* __restrict__ Wv,
                                __half* __restrict__ dst) {
    const long long per = (long long)LL * HH * EE * DHH;   // 2359296
    long long i8 = ((long long)blockIdx.x * 256 + threadIdx.x) * 8;
    if (i8 >= 3 * per) return;
    int mat = (int)(i8 / per);
    long long r = i8 % per;
    int d = (int)(r % DHH);                  // multiple of 8
    int e = (int)((r / DHH) % EE);
    int h = (int)((r / (DHH * EE)) % HH);
    int l = (int)(r / ((long long)DHH * EE * HH));
    const float* src = (mat == 0) ? Wq : (mat == 1) ? Wk : Wv;
    float4 v0 = *reinterpret_cast<const float4*>(src + r);
    float4 v1 = *reinterpret_cast<const float4*>(src + r + 4);
    __half2 hh[4];
    hh[0] = __floats2half2_rn(v0.x, v0.y);
    hh[1] = __floats2half2_rn(v0.z, v0.w);
    hh[2] = __floats2half2_rn(v1.x, v1.y);
    hh[3] = __floats2half2_rn(v1.z, v1.w);
    *reinterpret_cast<uint4*>(
        dst + ((long long)l * EE + e) * NQKV + mat * 768 + h * 64 + d) =
        *reinterpret_cast<uint4*>(hh);
}

// ---------------- layernorm: one block per row, fp16 out --------------------
__global__ void layernorm_kernel(const float* __restrict__ x,
                                 const float* __restrict__ w,
                                 const float* __restrict__ b,
                                 __half* __restrict__ out) {
    int row = blockIdx.x;
    const float* xr = x + (long long)row * EE;
    __half* orow = out + (long long)row * EE;
    int tid = threadIdx.x;  // 256

    float s = 0.f, s2 = 0.f;
    #pragma unroll
    for (int i = tid; i < EE; i += 256) {
        float v = xr[i];
        s += v; s2 += v * v;
    }
    __shared__ float rs[256], rs2[256];
    rs[tid] = s; rs2[tid] = s2;
    __syncthreads();
    for (int st = 128; st > 0; st >>= 1) {
        if (tid < st) { rs[tid] += rs[tid + st]; rs2[tid] += rs2[tid + st]; }
        __syncthreads();
    }
    float mu = rs[0] * (1.f / EE);
    float var = rs2[0] * (1.f / EE) - mu * mu;
    float rstd = rsqrtf(var + LN_EPS);
    #pragma unroll
    for (int i = tid; i < EE; i += 256) {
        orow[i] = __float2half_rn((xr[i] - mu) * rstd * w[i] + b[i]);
    }
}

// ---------------- fused flash attention -------------------------------------
// One block per (q-tile of 64, b*h). All intermediates in smem.
// qkv: packed [bs][mat*768 + h*64 + d].  o: [bs][h*64+d].
#define LDQ 72
#define LDK 72
#define LDP 264
#define LDSF 260
#define LDV 72
#define LDSO 68
#define SM_Q 0
#define SM_K 9216                      // 64*LDQ*2
#define SM_SF (SM_K + SP2 * LDK * 2)   // 9216+36864 = 46080
#define SM_OS (SM_SF + 40960)          // O staging inside Sf region
#define ATTN_SMEM (SM_SF + 64 * LDSF * 4)   // 112640 B

__global__ __launch_bounds__(256)
void fused_attn_kernel(const __half* __restrict__ qkv,
                       __half* __restrict__ o, float inv_scale) {
    extern __shared__ char sm[];
    __half* Qs = reinterpret_cast<__half*>(sm + SM_Q);   // 64 x LDQ
    __half* Ks = reinterpret_cast<__half*>(sm + SM_K);   // SP2 x LDK
    __half* Ph = Ks;                                     // 64 x LDP (reuse)
    float*  Sf = reinterpret_cast<float*>(sm + SM_SF);   // 64 x LDSF
    __half* Vs = reinterpret_cast<__half*>(sm + SM_SF);  // SP2 x LDV (reuse)
    float*  Os = reinterpret_cast<float*>(sm + SM_OS);   // 64 x LDSO

    int qt = blockIdx.x;          // 0..3
    int bh = blockIdx.y;          // b*HH + h
    int b = bh / HH, h = bh % HH;
    const __half* base = qkv + (long long)b * SS * NQKV + h * 64;
    int q0 = qt * 64;

    int tid = threadIdx.x;
    int wid = tid >> 5, lane = tid & 31;
    const uint4 z4 = {0u, 0u, 0u, 0u};

    // ---- load Q tile (64 x 64), zero-pad rows >= SS ----
    #pragma unroll
    for (int e = 0; e < 2; e++) {
        int i = tid + e * 256;
        int r = i >> 3, c = (i & 7) * 8;
        int gq = q0 + r;
        uint4 v = (gq < SS)
            ? *reinterpret_cast<const uint4*>(base + (long long)gq * NQKV + c)
            : z4;
        *reinterpret_cast<uint4*>(&Qs[r * LDQ + c]) = v;
    }
    // ---- load K (SP2 x 64), zero-pad rows >= SS ----
    #pragma unroll
    for (int e = 0; e < 8; e++) {
        int i = tid + e * 256;
        int r = i >> 3, c = (i & 7) * 8;
        uint4 v = (r < SS)
            ? *reinterpret_cast<const uint4*>(base + 768 +
                                              (long long)r * NQKV + c)
            : z4;
        *reinterpret_cast<uint4*>(&Ks[r * LDK + c]) = v;
    }
    __syncthreads();

    // ---- S = Q @ K^T : warp w -> cols [w*32, w*32+32), rows 0..63 ----
    {
        wmma::fragment<wmma::accumulator, 16, 16, 16, float> acc[4][2];
        #pragma unroll
        for (int i = 0; i < 4; i++)
            #pragma unroll
            for (int j = 0; j < 2; j++)
                wmma::fill_fragment(acc[i][j], 0.f);
        #pragma unroll
        for (int kt = 0; kt < 4; kt++) {
            wmma::fragment<wmma::matrix_a, 16, 16, 16, __half,
                           wmma::row_major> af[4];
            wmma::fragment<wmma::matrix_b, 16, 16, 16, __half,
                           wmma::col_major> bf[2];
            #pragma unroll
            for (int i = 0; i < 4; i++)
                wmma::load_matrix_sync(af[i],
                    Qs + (i * 16) * LDQ + kt * 16, LDQ);
            #pragma unroll
            for (int j = 0; j < 2; j++)
                wmma::load_matrix_sync(bf[j],
                    Ks + (wid * 32 + j * 16) * LDK + kt * 16, LDK);
            #pragma unroll
            for (int i = 0; i < 4; i++)
                #pragma unroll
                for (int j = 0; j < 2; j++)
                    wmma::mma_sync(acc[i][j], af[i], bf[j], acc[i][j]);
        }
        #pragma unroll
        for (int i = 0; i < 4; i++)
            #pragma unroll
            for (int j = 0; j < 2; j++)
                wmma::store_matrix_sync(
                    Sf + (i * 16) * LDSF + wid * 32 + j * 16, acc[i][j],
                    LDSF, wmma::mem_row_major);
    }
    __syncthreads();

    // ---- softmax per row (warp w owns rows w*8..w*8+7); write half P ----
    #pragma unroll
    for (int rr = 0; rr < 8; rr++) {
        int r = wid * 8 + rr;
        float m = -1e30f;
        for (int c = lane; c < SS; c += 32)
            m = fmaxf(m, Sf[r * LDSF + c] * inv_scale);
        #pragma unroll
        for (int off = 16; off > 0; off >>= 1)
            m = fmaxf(m, __shfl_xor_sync(0xffffffffu, m, off));
        float sum = 0.f;
        for (int c = lane; c < SS; c += 32) {
            float e = expf(Sf[r * LDSF + c] * inv_scale - m);
            Sf[r * LDSF + c] = e;
            sum += e;
        }
        #pragma unroll
        for (int off = 16; off > 0; off >>= 1)
            sum += __shfl_xor_sync(0xffffffffu, sum, off);
        float inv = 1.f / sum;
        for (int c = lane; c < SP2; c += 32)
            Ph[r * LDP + c] = (c < SS)
                ? __float2half_rn(Sf[r * LDSF + c] * inv) : __half(0.f);
    }
    __syncthreads();

    // ---- load V into Sf region (SP2 x 64), zero-pad rows >= SS ----
    #pragma unroll
    for (int e = 0; e < 8; e++) {
        int i = tid + e * 256;
        int r = i >> 3, c = (i & 7) * 8;
        uint4 v = (r < SS)
            ? *reinterpret_cast<const uint4*>(base + 1536 +
                                              (long long)r * NQKV + c)
            : z4;
        *reinterpret_cast<uint4*>(&Vs[r * LDV + c]) = v;
    }
    __syncthreads();

    // ---- O = P @ V : warp grid 4m x 2n, warp tile 16 x 32 ----
    {
        int wm = wid >> 1, wn = wid & 1;
        wmma::fragment<wmma::accumulator, 16, 16, 16, float> acc[2];
        wmma::fill_fragment(acc[0], 0.f);
        wmma::fill_fragment(acc[1], 0.f);
        #pragma unroll
        for (int kt = 0; kt < SP2 / 16; kt++) {
            wmma::fragment<wmma::matrix_a, 16, 16, 16, __half,
                           wmma::row_major> af;
            wmma::fragment<wmma::matrix_b, 16, 16, 16, __half,
                           wmma::row_major> bf[2];
            wmma::load_matrix_sync(af, Ph + (wm * 16) * LDP + kt * 16, LDP);
            #pragma unroll
            for (int j = 0; j < 2; j++)
                wmma::load_matrix_sync(bf[j],
                    Vs + (kt * 16) * LDV + wn * 32 + j * 16, LDV);
            #pragma unroll
            for (int j = 0; j < 2; j++)
                wmma::mma_sync(acc[j], af, bf[j], acc[j]);
        }
        #pragma unroll
        for (int j = 0; j < 2; j++)
            wmma::store_matrix_sync(
                Os + (wm * 16) * LDSO + wn * 32 + j * 16, acc[j],
                LDSO, wmma::mem_row_major);
    }
    __syncthreads();

    // ---- write O ----
    #pragma unroll
    for (int e = 0; e < 16; e++) {
        int i = tid + e * 256;
        int m = i >> 6, d = i & 63;
        int gq = q0 + m;
        if (gq < SS)
            o[((long long)b * SS + gq) * EE + h * 64 + d] =
                __float2half_rn(Os[m * LDSO + d]);
    }
}

// ---------------- FP16-native TC GEMM (fp32 accum) --------------------------
// EPI: 0: C=alpha*acc  1: C=gelu(acc+bias)  2: C=acc+D  3: C=acc+bias+D
template <int EPI, int BNT, bool OUTH>
__global__ __launch_bounds__(256)
void hgemm_kernel(const __half* __restrict__ A, const __half* __restrict__ Bm,
                  void* __restrict__ Cv,
                  const float* __restrict__ bias, const float* __restrict__ Dm,
                  int M, int N, int K, int lda, int ldb, int ldc, float alpha) {
    constexpr int BM = 128, BK = 32;
    constexpr int WCOLS  = (BNT == 128) ? 4 : 2;
    constexpr int WARP_M = (BNT == 128) ? 64 : 32;
    constexpr int WARP_N = 32;
    constexpr int AF = WARP_M / 16;
    constexpr int BF = WARP_N / 16;
    constexpr int LDA_H = BK + 8;
    constexpr int LDB_H = BNT + 8;
    constexpr int LDST = 68;
    constexpr int STAGE_HALFS = BM * LDA_H + BK * LDB_H;
    constexpr int EPI_BYTES = BM * LDST * 4;
    constexpr int SMEM_BYTES =
        (STAGE_HALFS * 2 > EPI_BYTES) ? STAGE_HALFS * 2 : EPI_BYTES;

    const int m0 = blockIdx.y * BM, n0 = blockIdx.x * BNT;

    __shared__ __align__(16) char smem_raw[SMEM_BYTES];
    __half* As = reinterpret_cast<__half*>(smem_raw);
    __half* Bs = As + BM * LDA_H;
    float*  epi = reinterpret_cast<float*>(smem_raw);

    int tid = threadIdx.x;
    int wid = tid >> 5;
    int wm = wid % (8 / WCOLS);
    int wn = wid / (8 / WCOLS);

    wmma::fragment<wmma::accumulator, 16, 16, 16, float> acc[AF][BF];
    #pragma unroll
    for (int i = 0; i < AF; i++)
        #pragma unroll
        for (int j = 0; j < BF; j++)
            wmma::fill_fragment(acc[i][j], 0.f);

    const uint4 z4 = {0u, 0u, 0u, 0u};

    for (int k0 = 0; k0 < K; k0 += BK) {
        #pragma unroll
        for (int e = 0; e < (BM * BK / 8) / 256; e++) {
            int i = tid + e * 256;
            int m = i >> 2, k = (i & 3) * 8;
            int gm = m0 + m;
            uint4 v = (gm < M)
                ? *reinterpret_cast<const uint4*>(A + (long long)gm * lda + k0 + k)
                : z4;
            *reinterpret_cast<uint4*>(&As[m * LDA_H + k]) = v;
        }
        {
            constexpr int VR = BNT / 8;
            #pragma unroll
            for (int e = 0; e < (BK * BNT / 8) / 256; e++) {
                int i = tid + e * 256;
                int k = i / VR, n = (i % VR) * 8;
                int gn = n0 + n;
                uint4 v = (gn < N)
                    ? *reinterpret_cast<const uint4*>(
                          Bm + (long long)(k0 + k) * ldb + gn)
                    : z4;
                *reinterpret_cast<uint4*>(&Bs[k * LDB_H + n]) = v;
            }
        }
        __syncthreads();

        #pragma unroll
        for (int kt = 0; kt < BK / 16; kt++) {
            wmma::fragment<wmma::matrix_a, 16, 16, 16, __half,
                           wmma::row_major> af[AF];
            wmma::fragment<wmma::matrix_b, 16, 16, 16, __half,
                           wmma::row_major> bf[BF];
            #pragma unroll
            for (int i = 0; i < AF; i++)
                wmma::load_matrix_sync(
                    af[i], As + (wm * WARP_M + i * 16) * LDA_H + kt * 16, LDA_H);
            #pragma unroll
            for (int j = 0; j < BF; j++)
                wmma::load_matrix_sync(
                    bf[j], Bs + (kt * 16) * LDB_H + wn * WARP_N + j * 16, LDB_H);
            #pragma unroll
            for (int i = 0; i < AF; i++)
                #pragma unroll
                for (int j = 0; j < BF; j++)
                    wmma::mma_sync(acc[i][j], af[i], bf[j], acc[i][j]);
        }
        __syncthreads();
    }

    constexpr int NHALF = (BNT == 128) ? 2 : 1;
    #pragma unroll
    for (int h = 0; h < NHALF; h++) {
        bool mywarp = (BNT == 128) ? ((wn >> 1) == h) : true;
        if (mywarp) {
            int cbase = (BNT == 128) ? (wn & 1) * 32 : wn * 32;
            #pragma unroll
            for (int i = 0; i < AF; i++)
                #pragma unroll
                for (int j = 0; j < BF; j++)
                    wmma::store_matrix_sync(
                        epi + (wm * WARP_M + i * 16) * LDST + cbase + j * 16,
                        acc[i][j], LDST, wmma::mem_row_major);
        }
        __syncthreads();

        int nl = tid & 63;
        int n = n0 + h * 64 + nl;
        if (n < N) {
            float bn_ = (EPI == 1 || EPI == 3) ? bias[n] : 0.f;
            #pragma unroll 8
            for (int p = 0; p < 32; p++) {
                int r = (tid >> 6) + p * 4;
                int m = m0 + r;
                if (m >= M) break;
                float v = epi[r * LDST + nl] * alpha;
                if (EPI == 1) {
                    v += bn_;
                    v = 0.5f * v * (1.f + erff(v * 0.70710678118654752f));
                } else if (EPI == 2) {
                    v += Dm[(long long)m * ldc + n];
                } else if (EPI == 3) {
                    v += bn_ + Dm[(long long)m * ldc + n];
                }
                if (OUTH)
                    ((__half*)Cv)[(long long)m * ldc + n] = __float2half_rn(v);
                else
                    ((float*)Cv)[(long long)m * ldc + n] = v;
            }
        }
        if (h + 1 < NHALF) __syncthreads();
    }
}

// ---------------- classifier + final softmax: one block per batch ------------
__global__ void classifier_kernel(const float* __restrict__ hbuf,
                                  const float* __restrict__ Wc,
                                  const float* __restrict__ bc,
                                  float* __restrict__ out) {
    int b = blockIdx.x;
    int tid = threadIdx.x;  // 256
    __shared__ float xs[EE];
    __shared__ float lg[CC];
    __shared__ float red[256];

    const float* xr = hbuf + (long long)b * SS * EE;  // row s=0
    for (int i = tid; i < EE; i += 256) xs[i] = xr[i];
    __syncthreads();

    for (int c = tid; c < CC; c += 256) {
        float acc = bc[c];
        for (int e = 0; e < EE; e++) acc += xs[e] * Wc[(long long)e * CC + c];
        lg[c] = acc;
    }
    __syncthreads();

    float m = -1e30f;
    for (int c = tid; c < CC; c += 256) m = fmaxf(m, lg[c]);
    red[tid] = m; __syncthreads();
    for (int st = 128; st > 0; st >>= 1) {
        if (tid < st) red[tid] = fmaxf(red[tid], red[tid + st]);
        __syncthreads();
    }
    m = red[0];
    __syncthreads();

    float sum = 0.f;
    for (int c = tid; c < CC; c += 256) {
        float e = expf(lg[c] - m);
        lg[c] = e; sum += e;
    }
    red[tid] = sum; __syncthreads();
    for (int st = 128; st > 0; st >>= 1) {
        if (tid < st) red[tid] += red[tid + st];
        __syncthreads();
    }
    float inv = 1.f / red[0];
    for (int c = tid; c < CC; c += 256)
        out[(long long)b * CC + c] = lg[c] * inv;
}

// ---------------- host orchestration ----------------------------------------
extern "C" void kernel_launch(void* const* d_in, const int* in_sizes, int n_in,
                              void* d_out, int out_size) {
    const float* x     = (const float*)d_in[0];
    const float* Wk    = (const float*)d_in[1];
    const float* Wq    = (const float*)d_in[2];
    const float* Wv    = (const float*)d_in[3];
    const float* Wconv = (const float*)d_in[4];
    const float* ln1_w = (const float*)d_in[5];
    const float* ln1_b = (const float*)d_in[6];
    const float* ln2_w = (const float*)d_in[7];
    const float* ln2_b = (const float*)d_in[8];
    const float* W1    = (const float*)d_in[9];
    const float* b1    = (const float*)d_in[10];
    const float* W2    = (const float*)d_in[11];
    const float* b2    = (const float*)d_in[12];
    const float* Wc    = (const float*)d_in[13];
    const float* bc    = (const float*)d_in[14];
    float* out = (float*)d_out;

    float *ph, *pres1;
    __half *pxnh, *pqkvh, *poh, *pffh, *pwqkv, *pwcv, *pw1, *pw2;
    cudaGetSymbolAddress((void**)&ph,     g_h);
    cudaGetSymbolAddress((void**)&pres1,  g_res1);
    cudaGetSymbolAddress((void**)&pxnh,   g_xnh);
    cudaGetSymbolAddress((void**)&pqkvh,  g_qkvh);
    cudaGetSymbolAddress((void**)&poh,    g_oh);
    cudaGetSymbolAddress((void**)&pffh,   g_ffh);
    cudaGetSymbolAddress((void**)&pwqkv,  g_wqkv);
    cudaGetSymbolAddress((void**)&pwcv,   g_wcv);
    cudaGetSymbolAddress((void**)&pw1,    g_w1);
    cudaGetSymbolAddress((void**)&pw2,    g_w2);

    cudaFuncSetAttribute(fused_attn_kernel,
                         cudaFuncAttributeMaxDynamicSharedMemorySize,
                         ATTN_SMEM);

    cudaMemcpyAsync(ph, x, sizeof(float) * (size_t)BS * EE,
                    cudaMemcpyDeviceToDevice);

    // ---- weight conversion pre-pass (vectorized) ----
    {
        long long nq8 = (3LL * LL * HH * EE * DHH) / 8;
        pack_qkv_kernel<<<(int)((nq8 + 255) / 256), 256>>>(Wq, Wk, Wv, pwqkv);
        int ncv8 = LL * EE * EE / 8;
        cvt_f2h_kernel<<<(ncv8 + 255) / 256, 256>>>(Wconv, pwcv, ncv8);
        int n18 = LL * EE * FF_ / 8;
        cvt_f2h_kernel<<<(n18 + 255) / 256, 256>>>(W1, pw1, n18);
        cvt_f2h_kernel<<<(n18 + 255) / 256, 256>>>(W2, pw2, n18);
    }

    const float inv_scale = 1.f / sqrtf((float)SS);
    const int MT = (BS + 127) / 128;  // 50 row tiles

    for (int l = 0; l < LL; l++) {
        const __half* wqkv_l = pwqkv + (long long)l * EE * NQKV;
        const __half* wcv_l  = pwcv + (long long)l * EE * EE;
        const __half* w1_l   = pw1 + (long long)l * EE * FF_;
        const __half* w2_l   = pw2 + (long long)l * FF_ * EE;
        const float* b1_l = b1 + (long long)l * FF_;
        const float* b2_l = b2 + (long long)l * EE;

        // LN1 -> half
        layernorm_kernel<<<BS, 256>>>(ph, ln1_w + l * EE, ln1_b + l * EE, pxnh);

        // packed QKV: [6304 x 768] @ [768 x 2304] -> half
        {
            dim3 g(NQKV / 128, MT, 1);
            hgemm_kernel<0, 128, true><<<g, 256>>>(
                pxnh, wqkv_l, pqkvh, nullptr, nullptr,
                BS, NQKV, EE, EE, NQKV, NQKV, 1.f);
        }

        // fused attention: QK^T -> softmax -> PV, all in smem
        {
            dim3 g((SS + 63) / 64, BB * HH);
            fused_attn_kernel<<<g, 256, ATTN_SMEM>>>(pqkvh, poh, inv_scale);
        }

        // res1 = O @ Wconv + h   (fp32 out)
        {
            dim3 g(EE / 128, MT, 1);
            hgemm_kernel<2, 128, false><<<g, 256>>>(
                poh, wcv_l, pres1, nullptr, ph,
                BS, EE, EE, EE, EE, EE, 1.f);
        }

        // LN2 -> half
        layernorm_kernel<<<BS, 256>>>(pres1, ln2_w + l * EE, ln2_b + l * EE,
                                      pxnh);

        // FF1 = gelu(xn2 @ W1 + b1) -> half
        {
            dim3 g(FF_ / 128, MT, 1);
            hgemm_kernel<1, 128, true><<<g, 256>>>(
                pxnh, w1_l, pffh, b1_l, nullptr,
                BS, FF_, EE, EE, FF_, FF_, 1.f);
        }

        // h = FF1 @ W2 + b2 + res1  (fp32 out)
        {
            dim3 g(EE / 128, MT, 1);
            hgemm_kernel<3, 128, false><<<g, 256>>>(
                pffh, w2_l, ph, b2_l, pres1,
                BS, EE, FF_, FF_, EE, EE, 1.f);
        }
    }

    // classifier + softmax
    classifier_kernel<<<BB, 256>>>(ph, Wc, bc, out);
}

// round 10
// speedup vs baseline: 4.4449x; 1.0497x over previous
#include <cuda_runtime.h>
#include <cuda_fp16.h>
#include <mma.h>
#include <math.h>
#include <stdint.h>

using namespace nvcuda;

// ---------------- problem constants ----------------
#define BB 32
#define SS 197
#define EE 768
#define HH 12
#define DHH 64
#define FF_ 2048
#define LL 4
#define CC 1000
#define BS (BB * SS)     // 6304
#define SP2 256          // padded key length inside fused attention
#define NQKV 2304        // 3 * H * DH packed output width
#define LN_EPS 1e-5f

// ---------------- scratch (device globals; allocation-free rule) ------------
__device__ float  g_h    [BS * EE];
__device__ float  g_res1 [BS * EE];
__device__ __half g_xnh  [BS * EE];
__device__ __half g_qkvh [(BS + 32) * NQKV];
__device__ __half g_oh   [BS * EE];
__device__ __half g_ffh  [BS * FF_];
// fp16 weights (converted once per launch)
__device__ __half g_wqkv [LL * EE * NQKV];
__device__ __half g_wcv  [LL * EE * EE];
__device__ __half g_w1   [LL * EE * FF_];
__device__ __half g_w2   [LL * FF_ * EE];

// ---------------- cp.async helpers ------------------------------------------
__device__ __forceinline__ void cp_async16(void* smem_dst, const void* gsrc,
                                           bool pred) {
    unsigned int s = (unsigned int)__cvta_generic_to_shared(smem_dst);
    int sz = pred ? 16 : 0;
    asm volatile("cp.async.cg.shared.global [%0], [%1], 16, %2;\n"
                 :: "r"(s), "l"(gsrc), "r"(sz));
}
__device__ __forceinline__ void cp_commit() {
    asm volatile("cp.async.commit_group;\n" ::: "memory");
}
__device__ __forceinline__ void cp_wait0() {
    asm volatile("cp.async.wait_group 0;\n" ::: "memory");
}

// ---------------- weight conversion (vectorized: 8 elems/thread) ------------
__global__ void cvt_f2h_kernel(const float* __restrict__ src,
                               __half* __restrict__ dst, int n8) {
    int i = blockIdx.x * 256 + threadIdx.x;
    if (i >= n8) return;
    long long o = (long long)i * 8;
    float4 v0 = *reinterpret_cast<const float4*>(src + o);
    float4 v1 = *reinterpret_cast<const float4*>(src + o + 4);
    __half2 h[4];
    h[0] = __floats2half2_rn(v0.x, v0.y);
    h[1] = __floats2half2_rn(v0.z, v0.w);
    h[2] = __floats2half2_rn(v1.x, v1.y);
    h[3] = __floats2half2_rn(v1.z, v1.w);
    *reinterpret_cast<uint4*>(dst + o) = *reinterpret_cast<uint4*>(h);
}

__global__ void pack_qkv_kernel(const float* __restrict__ Wq,
                                const float* __restrict__ Wk,
                                const float* __restrict__ Wv,
                                __half* __restrict__ dst) {
    const long long per = (long long)LL * HH * EE * DHH;   // 2359296
    long long i8 = ((long long)blockIdx.x * 256 + threadIdx.x) * 8;
    if (i8 >= 3 * per) return;
    int mat = (int)(i8 / per);
    long long r = i8 % per;
    int d = (int)(r % DHH);                  // multiple of 8
    int e = (int)((r / DHH) % EE);
    int h = (int)((r / (DHH * EE)) % HH);
    int l = (int)(r / ((long long)DHH * EE * HH));
    const float* src = (mat == 0) ? Wq : (mat == 1) ? Wk : Wv;
    float4 v0 = *reinterpret_cast<const float4*>(src + r);
    float4 v1 = *reinterpret_cast<const float4*>(src + r + 4);
    __half2 hh[4];
    hh[0] = __floats2half2_rn(v0.x, v0.y);
    hh[1] = __floats2half2_rn(v0.z, v0.w);
    hh[2] = __floats2half2_rn(v1.x, v1.y);
    hh[3] = __floats2half2_rn(v1.z, v1.w);
    *reinterpret_cast<uint4*>(
        dst + ((long long)l * EE + e) * NQKV + mat * 768 + h * 64 + d) =
        *reinterpret_cast<uint4*>(hh);
}

// ---------------- layernorm: one block per row, fp16 out --------------------
__global__ void layernorm_kernel(const float* __restrict__ x,
                                 const float* __restrict__ w,
                                 const float* __restrict__ b,
                                 __half* __restrict__ out) {
    int row = blockIdx.x;
    const float* xr = x + (long long)row * EE;
    __half* orow = out + (long long)row * EE;
    int tid = threadIdx.x;  // 256

    float s = 0.f, s2 = 0.f;
    #pragma unroll
    for (int i = tid; i < EE; i += 256) {
        float v = xr[i];
        s += v; s2 += v * v;
    }
    __shared__ float rs[256], rs2[256];
    rs[tid] = s; rs2[tid] = s2;
    __syncthreads();
    for (int st = 128; st > 0; st >>= 1) {
        if (tid < st) { rs[tid] += rs[tid + st]; rs2[tid] += rs2[tid + st]; }
        __syncthreads();
    }
    float mu = rs[0] * (1.f / EE);
    float var = rs2[0] * (1.f / EE) - mu * mu;
    float rstd = rsqrtf(var + LN_EPS);
    #pragma unroll
    for (int i = tid; i < EE; i += 256) {
        orow[i] = __float2half_rn((xr[i] - mu) * rstd * w[i] + b[i]);
    }
}

// ---------------- fused flash attention -------------------------------------
// One block per (q-tile of 64, b*h). All intermediates in smem.
#define LDQ 72
#define LDK 72
#define LDP 264
#define LDSF 260
#define LDV 72
#define LDSO 68
#define SM_Q 0
#define SM_K 9216                      // 64*LDQ*2
#define SM_SF (SM_K + SP2 * LDK * 2)   // 46080
#define SM_OS (SM_SF + 40960)
#define ATTN_SMEM (SM_SF + 64 * LDSF * 4)   // 112640 B

__global__ __launch_bounds__(256)
void fused_attn_kernel(const __half* __restrict__ qkv,
                       __half* __restrict__ o, float inv_scale) {
    extern __shared__ char sm[];
    __half* Qs = reinterpret_cast<__half*>(sm + SM_Q);
    __half* Ks = reinterpret_cast<__half*>(sm + SM_K);
    __half* Ph = Ks;
    float*  Sf = reinterpret_cast<float*>(sm + SM_SF);
    __half* Vs = reinterpret_cast<__half*>(sm + SM_SF);
    float*  Os = reinterpret_cast<float*>(sm + SM_OS);

    int qt = blockIdx.x;
    int bh = blockIdx.y;
    int b = bh / HH, h = bh % HH;
    const __half* base = qkv + (long long)b * SS * NQKV + h * 64;
    int q0 = qt * 64;

    int tid = threadIdx.x;
    int wid = tid >> 5, lane = tid & 31;
    const uint4 z4 = {0u, 0u, 0u, 0u};

    #pragma unroll
    for (int e = 0; e < 2; e++) {
        int i = tid + e * 256;
        int r = i >> 3, c = (i & 7) * 8;
        int gq = q0 + r;
        uint4 v = (gq < SS)
            ? *reinterpret_cast<const uint4*>(base + (long long)gq * NQKV + c)
            : z4;
        *reinterpret_cast<uint4*>(&Qs[r * LDQ + c]) = v;
    }
    #pragma unroll
    for (int e = 0; e < 8; e++) {
        int i = tid + e * 256;
        int r = i >> 3, c = (i & 7) * 8;
        uint4 v = (r < SS)
            ? *reinterpret_cast<const uint4*>(base + 768 +
                                              (long long)r * NQKV + c)
            : z4;
        *reinterpret_cast<uint4*>(&Ks[r * LDK + c]) = v;
    }
    __syncthreads();

    {
        wmma::fragment<wmma::accumulator, 16, 16, 16, float> acc[4][2];
        #pragma unroll
        for (int i = 0; i < 4; i++)
            #pragma unroll
            for (int j = 0; j < 2; j++)
                wmma::fill_fragment(acc[i][j], 0.f);
        #pragma unroll
        for (int kt = 0; kt < 4; kt++) {
            wmma::fragment<wmma::matrix_a, 16, 16, 16, __half,
                           wmma::row_major> af[4];
            wmma::fragment<wmma::matrix_b, 16, 16, 16, __half,
                           wmma::col_major> bf[2];
            #pragma unroll
            for (int i = 0; i < 4; i++)
                wmma::load_matrix_sync(af[i],
                    Qs + (i * 16) * LDQ + kt * 16, LDQ);
            #pragma unroll
            for (int j = 0; j < 2; j++)
                wmma::load_matrix_sync(bf[j],
                    Ks + (wid * 32 + j * 16) * LDK + kt * 16, LDK);
            #pragma unroll
            for (int i = 0; i < 4; i++)
                #pragma unroll
                for (int j = 0; j < 2; j++)
                    wmma::mma_sync(acc[i][j], af[i], bf[j], acc[i][j]);
        }
        #pragma unroll
        for (int i = 0; i < 4; i++)
            #pragma unroll
            for (int j = 0; j < 2; j++)
                wmma::store_matrix_sync(
                    Sf + (i * 16) * LDSF + wid * 32 + j * 16, acc[i][j],
                    LDSF, wmma::mem_row_major);
    }
    __syncthreads();

    #pragma unroll
    for (int rr = 0; rr < 8; rr++) {
        int r = wid * 8 + rr;
        float m = -1e30f;
        for (int c = lane; c < SS; c += 32)
            m = fmaxf(m, Sf[r * LDSF + c] * inv_scale);
        #pragma unroll
        for (int off = 16; off > 0; off >>= 1)
            m = fmaxf(m, __shfl_xor_sync(0xffffffffu, m, off));
        float sum = 0.f;
        for (int c = lane; c < SS; c += 32) {
            float e = expf(Sf[r * LDSF + c] * inv_scale - m);
            Sf[r * LDSF + c] = e;
            sum += e;
        }
        #pragma unroll
        for (int off = 16; off > 0; off >>= 1)
            sum += __shfl_xor_sync(0xffffffffu, sum, off);
        float inv = 1.f / sum;
        for (int c = lane; c < SP2; c += 32)
            Ph[r * LDP + c] = (c < SS)
                ? __float2half_rn(Sf[r * LDSF + c] * inv) : __half(0.f);
    }
    __syncthreads();

    #pragma unroll
    for (int e = 0; e < 8; e++) {
        int i = tid + e * 256;
        int r = i >> 3, c = (i & 7) * 8;
        uint4 v = (r < SS)
            ? *reinterpret_cast<const uint4*>(base + 1536 +
                                              (long long)r * NQKV + c)
            : z4;
        *reinterpret_cast<uint4*>(&Vs[r * LDV + c]) = v;
    }
    __syncthreads();

    {
        int wm = wid >> 1, wn = wid & 1;
        wmma::fragment<wmma::accumulator, 16, 16, 16, float> acc[2];
        wmma::fill_fragment(acc[0], 0.f);
        wmma::fill_fragment(acc[1], 0.f);
        #pragma unroll
        for (int kt = 0; kt < SP2 / 16; kt++) {
            wmma::fragment<wmma::matrix_a, 16, 16, 16, __half,
                           wmma::row_major> af;
            wmma::fragment<wmma::matrix_b, 16, 16, 16, __half,
                           wmma::row_major> bf[2];
            wmma::load_matrix_sync(af, Ph + (wm * 16) * LDP + kt * 16, LDP);
            #pragma unroll
            for (int j = 0; j < 2; j++)
                wmma::load_matrix_sync(bf[j],
                    Vs + (kt * 16) * LDV + wn * 32 + j * 16, LDV);
            #pragma unroll
            for (int j = 0; j < 2; j++)
                wmma::mma_sync(acc[j], af, bf[j], acc[j]);
        }
        #pragma unroll
        for (int j = 0; j < 2; j++)
            wmma::store_matrix_sync(
                Os + (wm * 16) * LDSO + wn * 32 + j * 16, acc[j],
                LDSO, wmma::mem_row_major);
    }
    __syncthreads();

    #pragma unroll
    for (int e = 0; e < 16; e++) {
        int i = tid + e * 256;
        int m = i >> 6, d = i & 63;
        int gq = q0 + m;
        if (gq < SS)
            o[((long long)b * SS + gq) * EE + h * 64 + d] =
                __float2half_rn(Os[m * LDSO + d]);
    }
}

// ---------------- FP16 TC GEMM: 128x128 tile, BK=32, cp.async 2-stage -------
// Requires: K % 32 == 0, N % 128 == 0, 16B-aligned rows (lda/ldb % 8 == 0).
// Only M may be ragged. One __syncthreads per k-iter; tile t+1 loads overlap
// compute(t).
// EPI: 0: C=acc  1: C=gelu(acc+bias)  2: C=acc+D  3: C=acc+bias+D
template <int EPI, bool OUTH>
__global__ __launch_bounds__(256)
void hgemm_kernel(const __half* __restrict__ A, const __half* __restrict__ Bm,
                  void* __restrict__ Cv,
                  const float* __restrict__ bias, const float* __restrict__ Dm,
                  int M, int N, int K, int lda, int ldb, int ldc) {
    constexpr int BM = 128, BNT = 128, BK = 32;
    constexpr int WARP_M = 64, WARP_N = 32;
    constexpr int AF = 4, BF = 2;
    constexpr int LDA_H = BK + 8;    // 40
    constexpr int LDB_H = BNT + 8;   // 136
    constexpr int LDST = 68;
    constexpr int STAGE_HALFS = BM * LDA_H + BK * LDB_H;  // 9472
    constexpr int PIPE_BYTES = 2 * STAGE_HALFS * 2;       // 37888
    constexpr int EPI_BYTES = BM * LDST * 4;              // 34816
    constexpr int SMEM_BYTES =
        (PIPE_BYTES > EPI_BYTES) ? PIPE_BYTES : EPI_BYTES;

    const int m0 = blockIdx.y * BM, n0 = blockIdx.x * BNT;

    __shared__ __align__(16) char smem_raw[SMEM_BYTES];
    float* epi = reinterpret_cast<float*>(smem_raw);

    int tid = threadIdx.x;
    int wid = tid >> 5;
    int wm = wid & 1, wn = wid >> 1;   // 2 x 4 warp grid (64m x 32n tiles)

    wmma::fragment<wmma::accumulator, 16, 16, 16, float> acc[AF][BF];
    #pragma unroll
    for (int i = 0; i < AF; i++)
        #pragma unroll
        for (int j = 0; j < BF; j++)
            wmma::fill_fragment(acc[i][j], 0.f);

    // per-thread fixed copy coordinates
    const int am = tid >> 2, ak = (tid & 3) * 8;           // A: 128x32
    const int bk = tid >> 4, bn = (tid & 15) * 8;          // B: first 16 k-rows
    const bool apred0 = (m0 + am < M);
    const bool apred1 = (m0 + am + 64 < M);
    const long long arow0 = (long long)(apred0 ? (m0 + am) : (M - 1)) * lda;
    const long long arow1 = (long long)(apred1 ? (m0 + am + 64) : (M - 1)) * lda;

    auto loadStage = [&](int t, int s) {
        __half* As = reinterpret_cast<__half*>(smem_raw) + s * STAGE_HALFS;
        __half* Bs = As + BM * LDA_H;
        int k0 = t * BK;
        // A: 128x32 = 512 vec16 -> 2 per thread
        cp_async16(&As[am * LDA_H + ak], A + arow0 + k0 + ak, apred0);
        cp_async16(&As[(am + 64) * LDA_H + ak], A + arow1 + k0 + ak, apred1);
        // B: 32x128 = 512 vec16 -> 2 per thread (k rows 0-15, 16-31)
        cp_async16(&Bs[bk * LDB_H + bn],
                   Bm + (long long)(k0 + bk) * ldb + n0 + bn, true);
        cp_async16(&Bs[(bk + 16) * LDB_H + bn],
                   Bm + (long long)(k0 + bk + 16) * ldb + n0 + bn, true);
        cp_commit();
    };

    auto compute = [&](int s) {
        const __half* As = reinterpret_cast<const __half*>(smem_raw)
                           + s * STAGE_HALFS;
        const __half* Bs = As + BM * LDA_H;
        #pragma unroll
        for (int kt = 0; kt < BK / 16; kt++) {
            wmma::fragment<wmma::matrix_a, 16, 16, 16, __half,
                           wmma::row_major> af[AF];
            wmma::fragment<wmma::matrix_b, 16, 16, 16, __half,
                           wmma::row_major> bf[BF];
            #pragma unroll
            for (int i = 0; i < AF; i++)
                wmma::load_matrix_sync(
                    af[i], As + (wm * WARP_M + i * 16) * LDA_H + kt * 16,
                    LDA_H);
            #pragma unroll
            for (int j = 0; j < BF; j++)
                wmma::load_matrix_sync(
                    bf[j], Bs + (kt * 16) * LDB_H + wn * WARP_N + j * 16,
                    LDB_H);
            #pragma unroll
            for (int i = 0; i < AF; i++)
                #pragma unroll
                for (int j = 0; j < BF; j++)
                    wmma::mma_sync(acc[i][j], af[i], bf[j], acc[i][j]);
        }
    };

    // ---- 2-stage cp.async pipeline, one barrier per iter ----
    const int nk = K / BK;
    loadStage(0, 0);
    for (int t = 0; t < nk; t++) {
        cp_wait0();
        __syncthreads();
        if (t + 1 < nk) loadStage(t + 1, (t + 1) & 1);
        compute(t & 1);
    }
    __syncthreads();

    // ---- epilogue: two 64-wide column halves staged through fp32 smem ----
    #pragma unroll
    for (int h = 0; h < 2; h++) {
        if ((wn >> 1) == h) {
            int cbase = (wn & 1) * 32;
            #pragma unroll
            for (int i = 0; i < AF; i++)
                #pragma unroll
                for (int j = 0; j < BF; j++)
                    wmma::store_matrix_sync(
                        epi + (wm * WARP_M + i * 16) * LDST + cbase + j * 16,
                        acc[i][j], LDST, wmma::mem_row_major);
        }
        __syncthreads();

        int nl = tid & 63;
        int n = n0 + h * 64 + nl;
        {
            float bn_ = (EPI == 1 || EPI == 3) ? bias[n] : 0.f;
            #pragma unroll 8
            for (int p = 0; p < 32; p++) {
                int r = (tid >> 6) + p * 4;
                int m = m0 + r;
                if (m >= M) break;
                float v = epi[r * LDST + nl];
                if (EPI == 1) {
                    v += bn_;
                    v = 0.5f * v * (1.f + erff(v * 0.70710678118654752f));
                } else if (EPI == 2) {
                    v += Dm[(long long)m * ldc + n];
                } else if (EPI == 3) {
                    v += bn_ + Dm[(long long)m * ldc + n];
                }
                if (OUTH)
                    ((__half*)Cv)[(long long)m * ldc + n] = __float2half_rn(v);
                else
                    ((float*)Cv)[(long long)m * ldc + n] = v;
            }
        }
        if (h == 0) __syncthreads();
    }
}

// ---------------- classifier + final softmax: one block per batch ------------
__global__ void classifier_kernel(const float* __restrict__ hbuf,
                                  const float* __restrict__ Wc,
                                  const float* __restrict__ bc,
                                  float* __restrict__ out) {
    int b = blockIdx.x;
    int tid = threadIdx.x;  // 256
    __shared__ float xs[EE];
    __shared__ float lg[CC];
    __shared__ float red[256];

    const float* xr = hbuf + (long long)b * SS * EE;  // row s=0
    for (int i = tid; i < EE; i += 256) xs[i] = xr[i];
    __syncthreads();

    for (int c = tid; c < CC; c += 256) {
        float acc = bc[c];
        for (int e = 0; e < EE; e++) acc += xs[e] * Wc[(long long)e * CC + c];
        lg[c] = acc;
    }
    __syncthreads();

    float m = -1e30f;
    for (int c = tid; c < CC; c += 256) m = fmaxf(m, lg[c]);
    red[tid] = m; __syncthreads();
    for (int st = 128; st > 0; st >>= 1) {
        if (tid < st) red[tid] = fmaxf(red[tid], red[tid + st]);
        __syncthreads();
    }
    m = red[0];
    __syncthreads();

    float sum = 0.f;
    for (int c = tid; c < CC; c += 256) {
        float e = expf(lg[c] - m);
        lg[c] = e; sum += e;
    }
    red[tid] = sum; __syncthreads();
    for (int st = 128; st > 0; st >>= 1) {
        if (tid < st) red[tid] += red[tid + st];
        __syncthreads();
    }
    float inv = 1.f / red[0];
    for (int c = tid; c < CC; c += 256)
        out[(long long)b * CC + c] = lg[c] * inv;
}

// ---------------- host orchestration ----------------------------------------
extern "C" void kernel_launch(void* const* d_in, const int* in_sizes, int n_in,
                              void* d_out, int out_size) {
    const float* x     = (const float*)d_in[0];
    const float* Wk    = (const float*)d_in[1];
    const float* Wq    = (const float*)d_in[2];
    const float* Wv    = (const float*)d_in[3];
    const float* Wconv = (const float*)d_in[4];
    const float* ln1_w = (const float*)d_in[5];
    const float* ln1_b = (const float*)d_in[6];
    const float* ln2_w = (const float*)d_in[7];
    const float* ln2_b = (const float*)d_in[8];
    const float* W1    = (const float*)d_in[9];
    const float* b1    = (const float*)d_in[10];
    const float* W2    = (const float*)d_in[11];
    const float* b2    = (const float*)d_in[12];
    const float* Wc    = (const float*)d_in[13];
    const float* bc    = (const float*)d_in[14];
    float* out = (float*)d_out;

    float *ph, *pres1;
    __half *pxnh, *pqkvh, *poh, *pffh, *pwqkv, *pwcv, *pw1, *pw2;
    cudaGetSymbolAddress((void**)&ph,     g_h);
    cudaGetSymbolAddress((void**)&pres1,  g_res1);
    cudaGetSymbolAddress((void**)&pxnh,   g_xnh);
    cudaGetSymbolAddress((void**)&pqkvh,  g_qkvh);
    cudaGetSymbolAddress((void**)&poh,    g_oh);
    cudaGetSymbolAddress((void**)&pffh,   g_ffh);
    cudaGetSymbolAddress((void**)&pwqkv,  g_wqkv);
    cudaGetSymbolAddress((void**)&pwcv,   g_wcv);
    cudaGetSymbolAddress((void**)&pw1,    g_w1);
    cudaGetSymbolAddress((void**)&pw2,    g_w2);

    cudaFuncSetAttribute(fused_attn_kernel,
                         cudaFuncAttributeMaxDynamicSharedMemorySize,
                         ATTN_SMEM);

    cudaMemcpyAsync(ph, x, sizeof(float) * (size_t)BS * EE,
                    cudaMemcpyDeviceToDevice);

    // ---- weight conversion pre-pass (vectorized) ----
    {
        long long nq8 = (3LL * LL * HH * EE * DHH) / 8;
        pack_qkv_kernel<<<(int)((nq8 + 255) / 256), 256>>>(Wq, Wk, Wv, pwqkv);
        int ncv8 = LL * EE * EE / 8;
        cvt_f2h_kernel<<<(ncv8 + 255) / 256, 256>>>(Wconv, pwcv, ncv8);
        int n18 = LL * EE * FF_ / 8;
        cvt_f2h_kernel<<<(n18 + 255) / 256, 256>>>(W1, pw1, n18);
        cvt_f2h_kernel<<<(n18 + 255) / 256, 256>>>(W2, pw2, n18);
    }

    const float inv_scale = 1.f / sqrtf((float)SS);
    const int MT = (BS + 127) / 128;  // 50 row tiles

    for (int l = 0; l < LL; l++) {
        const __half* wqkv_l = pwqkv + (long long)l * EE * NQKV;
        const __half* wcv_l  = pwcv + (long long)l * EE * EE;
        const __half* w1_l   = pw1 + (long long)l * EE * FF_;
        const __half* w2_l   = pw2 + (long long)l * FF_ * EE;
        const float* b1_l = b1 + (long long)l * FF_;
        const float* b2_l = b2 + (long long)l * EE;

        // LN1 -> half
        layernorm_kernel<<<BS, 256>>>(ph, ln1_w + l * EE, ln1_b + l * EE, pxnh);

        // packed QKV: [6304 x 768] @ [768 x 2304] -> half
        {
            dim3 g(NQKV / 128, MT, 1);
            hgemm_kernel<0, true><<<g, 256>>>(
                pxnh, wqkv_l, pqkvh, nullptr, nullptr,
                BS, NQKV, EE, EE, NQKV, NQKV);
        }

        // fused attention: QK^T -> softmax -> PV, all in smem
        {
            dim3 g((SS + 63) / 64, BB * HH);
            fused_attn_kernel<<<g, 256, ATTN_SMEM>>>(pqkvh, poh, inv_scale);
        }

        // res1 = O @ Wconv + h   (fp32 out)
        {
            dim3 g(EE / 128, MT, 1);
            hgemm_kernel<2, false><<<g, 256>>>(
                poh, wcv_l, pres1, nullptr, ph,
                BS, EE, EE, EE, EE, EE);
        }

        // LN2 -> half
        layernorm_kernel<<<BS, 256>>>(pres1, ln2_w + l * EE, ln2_b + l * EE,
                                      pxnh);

        // FF1 = gelu(xn2 @ W1 + b1) -> half
        {
            dim3 g(FF_ / 128, MT, 1);
            hgemm_kernel<1, true><<<g, 256>>>(
                pxnh, w1_l, pffh, b1_l, nullptr,
                BS, FF_, EE, EE, FF_, FF_);
        }

        // h = FF1 @ W2 + b2 + res1  (fp32 out)
        {
            dim3 g(EE / 128, MT, 1);
            hgemm_kernel<3, false><<<g, 256>>>(
                pffh, w2_l, ph, b2_l, pres1,
                BS, EE, FF_, FF_, EE, EE);
        }
    }

    // classifier + softmax
    classifier_kernel<<<BB, 256>>>(ph, Wc, bc, out);
}

// round 11
// speedup vs baseline: 4.6006x; 1.0350x over previous
#include <cuda_runtime.h>
#include <cuda_fp16.h>
#include <mma.h>
#include <math.h>
#include <stdint.h>

using namespace nvcuda;

// ---------------- problem constants ----------------
#define BB 32
#define SS 197
#define EE 768
#define HH 12
#define DHH 64
#define FF_ 2048
#define LL 4
#define CC 1000
#define BS (BB * SS)     // 6304
#define SP2 256          // padded key length inside fused attention
#define NQKV 2304        // 3 * H * DH packed output width
#define LN_EPS 1e-5f

// ---------------- scratch (device globals; allocation-free rule) ------------
__device__ float  g_h    [BS * EE];
__device__ float  g_res1 [BS * EE];
__device__ __half g_xnh  [BS * EE];
__device__ __half g_qkvh [(BS + 32) * NQKV];
__device__ __half g_oh   [BS * EE];
__device__ __half g_ffh  [BS * FF_];
// fp16 weights (converted once per launch)
__device__ __half g_wqkv [LL * EE * NQKV];
__device__ __half g_wcv  [LL * EE * EE];
__device__ __half g_w1   [LL * EE * FF_];
__device__ __half g_w2   [LL * FF_ * EE];

// ---------------- cp.async helpers ------------------------------------------
__device__ __forceinline__ void cp_async16(void* smem_dst, const void* gsrc,
                                           bool pred) {
    unsigned int s = (unsigned int)__cvta_generic_to_shared(smem_dst);
    int sz = pred ? 16 : 0;
    asm volatile("cp.async.cg.shared.global [%0], [%1], 16, %2;\n"
                 :: "r"(s), "l"(gsrc), "r"(sz));
}
__device__ __forceinline__ void cp_commit() {
    asm volatile("cp.async.commit_group;\n" ::: "memory");
}
template <int N>
__device__ __forceinline__ void cp_wait() {
    asm volatile("cp.async.wait_group %0;\n" :: "n"(N) : "memory");
}

// ---------------- weight conversion (vectorized: 8 elems/thread) ------------
__global__ void cvt_f2h_kernel(const float* __restrict__ src,
                               __half* __restrict__ dst, int n8) {
    int i = blockIdx.x * 256 + threadIdx.x;
    if (i >= n8) return;
    long long o = (long long)i * 8;
    float4 v0 = *reinterpret_cast<const float4*>(src + o);
    float4 v1 = *reinterpret_cast<const float4*>(src + o + 4);
    __half2 h[4];
    h[0] = __floats2half2_rn(v0.x, v0.y);
    h[1] = __floats2half2_rn(v0.z, v0.w);
    h[2] = __floats2half2_rn(v1.x, v1.y);
    h[3] = __floats2half2_rn(v1.z, v1.w);
    *reinterpret_cast<uint4*>(dst + o) = *reinterpret_cast<uint4*>(h);
}

__global__ void pack_qkv_kernel(const float* __restrict__ Wq,
                                const float* __restrict__ Wk,
                                const float* __restrict__ Wv,
                                __half* __restrict__ dst) {
    const long long per = (long long)LL * HH * EE * DHH;   // 2359296
    long long i8 = ((long long)blockIdx.x * 256 + threadIdx.x) * 8;
    if (i8 >= 3 * per) return;
    int mat = (int)(i8 / per);
    long long r = i8 % per;
    int d = (int)(r % DHH);                  // multiple of 8
    int e = (int)((r / DHH) % EE);
    int h = (int)((r / (DHH * EE)) % HH);
    int l = (int)(r / ((long long)DHH * EE * HH));
    const float* src = (mat == 0) ? Wq : (mat == 1) ? Wk : Wv;
    float4 v0 = *reinterpret_cast<const float4*>(src + r);
    float4 v1 = *reinterpret_cast<const float4*>(src + r + 4);
    __half2 hh[4];
    hh[0] = __floats2half2_rn(v0.x, v0.y);
    hh[1] = __floats2half2_rn(v0.z, v0.w);
    hh[2] = __floats2half2_rn(v1.x, v1.y);
    hh[3] = __floats2half2_rn(v1.z, v1.w);
    *reinterpret_cast<uint4*>(
        dst + ((long long)l * EE + e) * NQKV + mat * 768 + h * 64 + d) =
        *reinterpret_cast<uint4*>(hh);
}

// ---------------- layernorm: warp per row (shuffle-only), fp16 out ----------
__global__ __launch_bounds__(256)
void layernorm_kernel(const float* __restrict__ x,
                      const float* __restrict__ w,
                      const float* __restrict__ b,
                      __half* __restrict__ out) {
    int wid = threadIdx.x >> 5, lane = threadIdx.x & 31;
    int row = blockIdx.x * 8 + wid;
    if (row >= BS) return;
    const float* xr = x + (long long)row * EE;
    __half* orow = out + (long long)row * EE;

    float v[24];
    float s = 0.f, s2 = 0.f;
    #pragma unroll
    for (int j = 0; j < 24; j++) {
        v[j] = xr[lane + j * 32];
        s += v[j]; s2 += v[j] * v[j];
    }
    #pragma unroll
    for (int off = 16; off > 0; off >>= 1) {
        s  += __shfl_xor_sync(0xffffffffu, s, off);
        s2 += __shfl_xor_sync(0xffffffffu, s2, off);
    }
    float mu = s * (1.f / EE);
    float var = s2 * (1.f / EE) - mu * mu;
    float rstd = rsqrtf(var + LN_EPS);
    #pragma unroll
    for (int j = 0; j < 24; j++) {
        int i = lane + j * 32;
        orow[i] = __float2half_rn((v[j] - mu) * rstd * w[i] + b[i]);
    }
}

// ---------------- fused flash attention -------------------------------------
// One block per (q-tile of 64, b*h). All intermediates in smem.
#define LDQ 72
#define LDK 72
#define LDP 264
#define LDSF 260
#define LDV 72
#define LDSO 68
#define SM_Q 0
#define SM_K 9216                      // 64*LDQ*2
#define SM_SF (SM_K + SP2 * LDK * 2)   // 46080
#define SM_OS (SM_SF + 40960)
#define ATTN_SMEM (SM_SF + 64 * LDSF * 4)   // 112640 B

__global__ __launch_bounds__(256)
void fused_attn_kernel(const __half* __restrict__ qkv,
                       __half* __restrict__ o, float inv_scale) {
    extern __shared__ char sm[];
    __half* Qs = reinterpret_cast<__half*>(sm + SM_Q);
    __half* Ks = reinterpret_cast<__half*>(sm + SM_K);
    __half* Ph = Ks;
    float*  Sf = reinterpret_cast<float*>(sm + SM_SF);
    __half* Vs = reinterpret_cast<__half*>(sm + SM_SF);
    float*  Os = reinterpret_cast<float*>(sm + SM_OS);

    int qt = blockIdx.x;
    int bh = blockIdx.y;
    int b = bh / HH, h = bh % HH;
    const __half* base = qkv + (long long)b * SS * NQKV + h * 64;
    int q0 = qt * 64;

    int tid = threadIdx.x;
    int wid = tid >> 5, lane = tid & 31;
    const uint4 z4 = {0u, 0u, 0u, 0u};

    #pragma unroll
    for (int e = 0; e < 2; e++) {
        int i = tid + e * 256;
        int r = i >> 3, c = (i & 7) * 8;
        int gq = q0 + r;
        uint4 v = (gq < SS)
            ? *reinterpret_cast<const uint4*>(base + (long long)gq * NQKV + c)
            : z4;
        *reinterpret_cast<uint4*>(&Qs[r * LDQ + c]) = v;
    }
    #pragma unroll
    for (int e = 0; e < 8; e++) {
        int i = tid + e * 256;
        int r = i >> 3, c = (i & 7) * 8;
        uint4 v = (r < SS)
            ? *reinterpret_cast<const uint4*>(base + 768 +
                                              (long long)r * NQKV + c)
            : z4;
        *reinterpret_cast<uint4*>(&Ks[r * LDK + c]) = v;
    }
    __syncthreads();

    {
        wmma::fragment<wmma::accumulator, 16, 16, 16, float> acc[4][2];
        #pragma unroll
        for (int i = 0; i < 4; i++)
            #pragma unroll
            for (int j = 0; j < 2; j++)
                wmma::fill_fragment(acc[i][j], 0.f);
        #pragma unroll
        for (int kt = 0; kt < 4; kt++) {
            wmma::fragment<wmma::matrix_a, 16, 16, 16, __half,
                           wmma::row_major> af[4];
            wmma::fragment<wmma::matrix_b, 16, 16, 16, __half,
                           wmma::col_major> bf[2];
            #pragma unroll
            for (int i = 0; i < 4; i++)
                wmma::load_matrix_sync(af[i],
                    Qs + (i * 16) * LDQ + kt * 16, LDQ);
            #pragma unroll
            for (int j = 0; j < 2; j++)
                wmma::load_matrix_sync(bf[j],
                    Ks + (wid * 32 + j * 16) * LDK + kt * 16, LDK);
            #pragma unroll
            for (int i = 0; i < 4; i++)
                #pragma unroll
                for (int j = 0; j < 2; j++)
                    wmma::mma_sync(acc[i][j], af[i], bf[j], acc[i][j]);
        }
        #pragma unroll
        for (int i = 0; i < 4; i++)
            #pragma unroll
            for (int j = 0; j < 2; j++)
                wmma::store_matrix_sync(
                    Sf + (i * 16) * LDSF + wid * 32 + j * 16, acc[i][j],
                    LDSF, wmma::mem_row_major);
    }
    __syncthreads();

    #pragma unroll
    for (int rr = 0; rr < 8; rr++) {
        int r = wid * 8 + rr;
        float m = -1e30f;
        for (int c = lane; c < SS; c += 32)
            m = fmaxf(m, Sf[r * LDSF + c] * inv_scale);
        #pragma unroll
        for (int off = 16; off > 0; off >>= 1)
            m = fmaxf(m, __shfl_xor_sync(0xffffffffu, m, off));
        float sum = 0.f;
        for (int c = lane; c < SS; c += 32) {
            float e = expf(Sf[r * LDSF + c] * inv_scale - m);
            Sf[r * LDSF + c] = e;
            sum += e;
        }
        #pragma unroll
        for (int off = 16; off > 0; off >>= 1)
            sum += __shfl_xor_sync(0xffffffffu, sum, off);
        float inv = 1.f / sum;
        for (int c = lane; c < SP2; c += 32)
            Ph[r * LDP + c] = (c < SS)
                ? __float2half_rn(Sf[r * LDSF + c] * inv) : __half(0.f);
    }
    __syncthreads();

    #pragma unroll
    for (int e = 0; e < 8; e++) {
        int i = tid + e * 256;
        int r = i >> 3, c = (i & 7) * 8;
        uint4 v = (r < SS)
            ? *reinterpret_cast<const uint4*>(base + 1536 +
                                              (long long)r * NQKV + c)
            : z4;
        *reinterpret_cast<uint4*>(&Vs[r * LDV + c]) = v;
    }
    __syncthreads();

    {
        int wm = wid >> 1, wn = wid & 1;
        wmma::fragment<wmma::accumulator, 16, 16, 16, float> acc[2];
        wmma::fill_fragment(acc[0], 0.f);
        wmma::fill_fragment(acc[1], 0.f);
        #pragma unroll
        for (int kt = 0; kt < SP2 / 16; kt++) {
            wmma::fragment<wmma::matrix_a, 16, 16, 16, __half,
                           wmma::row_major> af;
            wmma::fragment<wmma::matrix_b, 16, 16, 16, __half,
                           wmma::row_major> bf[2];
            wmma::load_matrix_sync(af, Ph + (wm * 16) * LDP + kt * 16, LDP);
            #pragma unroll
            for (int j = 0; j < 2; j++)
                wmma::load_matrix_sync(bf[j],
                    Vs + (kt * 16) * LDV + wn * 32 + j * 16, LDV);
            #pragma unroll
            for (int j = 0; j < 2; j++)
                wmma::mma_sync(acc[j], af, bf[j], acc[j]);
        }
        #pragma unroll
        for (int j = 0; j < 2; j++)
            wmma::store_matrix_sync(
                Os + (wm * 16) * LDSO + wn * 32 + j * 16, acc[j],
                LDSO, wmma::mem_row_major);
    }
    __syncthreads();

    #pragma unroll
    for (int e = 0; e < 16; e++) {
        int i = tid + e * 256;
        int m = i >> 6, d = i & 63;
        int gq = q0 + m;
        if (gq < SS)
            o[((long long)b * SS + gq) * EE + h * 64 + d] =
                __float2half_rn(Os[m * LDSO + d]);
    }
}

// ---------------- FP16 TC GEMM: 128x128 tile, BK=32, cp.async 3-stage -------
// Requires: K % 32 == 0, N % 128 == 0, 16B-aligned rows (lda/ldb % 8 == 0).
// Only M may be ragged. 3-stage pipeline, wait_group 1: compute(t) overlaps
// the tail of load(t+1) plus all of load(t+2).
// EPI: 0: C=acc  1: C=gelu(acc+bias)  2: C=acc+D  3: C=acc+bias+D
#define HG_LDA 40
#define HG_LDB 136
#define HG_STAGE_HALFS (128 * HG_LDA + 32 * HG_LDB)   // 9472
#define HG_SMEM (3 * HG_STAGE_HALFS * 2)              // 56832 (> epi 34816)

template <int EPI, bool OUTH>
__global__ __launch_bounds__(256)
void hgemm_kernel(const __half* __restrict__ A, const __half* __restrict__ Bm,
                  void* __restrict__ Cv,
                  const float* __restrict__ bias, const float* __restrict__ Dm,
                  int M, int N, int K, int lda, int ldb, int ldc) {
    constexpr int BM = 128, BK = 32;
    constexpr int WARP_M = 64, WARP_N = 32;
    constexpr int AF = 4, BF = 2;
    constexpr int LDA_H = HG_LDA;
    constexpr int LDB_H = HG_LDB;
    constexpr int LDST = 68;

    const int m0 = blockIdx.y * BM, n0 = blockIdx.x * 128;

    extern __shared__ __align__(16) char smem_raw[];
    float* epi = reinterpret_cast<float*>(smem_raw);

    int tid = threadIdx.x;
    int wid = tid >> 5;
    int wm = wid & 1, wn = wid >> 1;   // 2 x 4 warp grid (64m x 32n tiles)

    wmma::fragment<wmma::accumulator, 16, 16, 16, float> acc[AF][BF];
    #pragma unroll
    for (int i = 0; i < AF; i++)
        #pragma unroll
        for (int j = 0; j < BF; j++)
            wmma::fill_fragment(acc[i][j], 0.f);

    // per-thread fixed copy coordinates
    const int am = tid >> 2, ak = (tid & 3) * 8;           // A: 128x32
    const int bk = tid >> 4, bn = (tid & 15) * 8;          // B: first 16 k-rows
    const bool apred0 = (m0 + am < M);
    const bool apred1 = (m0 + am + 64 < M);
    const long long arow0 = (long long)(apred0 ? (m0 + am) : (M - 1)) * lda;
    const long long arow1 = (long long)(apred1 ? (m0 + am + 64) : (M - 1)) * lda;

    auto loadStage = [&](int t, int s) {
        __half* As = reinterpret_cast<__half*>(smem_raw) + s * HG_STAGE_HALFS;
        __half* Bs = As + BM * LDA_H;
        int k0 = t * BK;
        cp_async16(&As[am * LDA_H + ak], A + arow0 + k0 + ak, apred0);
        cp_async16(&As[(am + 64) * LDA_H + ak], A + arow1 + k0 + ak, apred1);
        cp_async16(&Bs[bk * LDB_H + bn],
                   Bm + (long long)(k0 + bk) * ldb + n0 + bn, true);
        cp_async16(&Bs[(bk + 16) * LDB_H + bn],
                   Bm + (long long)(k0 + bk + 16) * ldb + n0 + bn, true);
        cp_commit();
    };

    auto compute = [&](int s) {
        const __half* As = reinterpret_cast<const __half*>(smem_raw)
                           + s * HG_STAGE_HALFS;
        const __half* Bs = As + BM * LDA_H;
        #pragma unroll
        for (int kt = 0; kt < BK / 16; kt++) {
            wmma::fragment<wmma::matrix_a, 16, 16, 16, __half,
                           wmma::row_major> af[AF];
            wmma::fragment<wmma::matrix_b, 16, 16, 16, __half,
                           wmma::row_major> bf[BF];
            #pragma unroll
            for (int i = 0; i < AF; i++)
                wmma::load_matrix_sync(
                    af[i], As + (wm * WARP_M + i * 16) * LDA_H + kt * 16,
                    LDA_H);
            #pragma unroll
            for (int j = 0; j < BF; j++)
                wmma::load_matrix_sync(
                    bf[j], Bs + (kt * 16) * LDB_H + wn * WARP_N + j * 16,
                    LDB_H);
            #pragma unroll
            for (int i = 0; i < AF; i++)
                #pragma unroll
                for (int j = 0; j < BF; j++)
                    wmma::mma_sync(acc[i][j], af[i], bf[j], acc[i][j]);
        }
    };

    // ---- 3-stage cp.async pipeline, one barrier per iter ----
    const int nk = K / BK;
    loadStage(0, 0);
    if (nk > 1) loadStage(1, 1);
    for (int t = 0; t < nk; t++) {
        if (t + 1 < nk) cp_wait<1>(); else cp_wait<0>();
        __syncthreads();
        if (t + 2 < nk) loadStage(t + 2, (t + 2) % 3);
        compute(t % 3);
    }
    __syncthreads();

    // ---- epilogue: two 64-wide column halves staged through fp32 smem ----
    #pragma unroll
    for (int h = 0; h < 2; h++) {
        if ((wn >> 1) == h) {
            int cbase = (wn & 1) * 32;
            #pragma unroll
            for (int i = 0; i < AF; i++)
                #pragma unroll
                for (int j = 0; j < BF; j++)
                    wmma::store_matrix_sync(
                        epi + (wm * WARP_M + i * 16) * LDST + cbase + j * 16,
                        acc[i][j], LDST, wmma::mem_row_major);
        }
        __syncthreads();

        int nl = tid & 63;
        int n = n0 + h * 64 + nl;
        {
            float bn_ = (EPI == 1 || EPI == 3) ? bias[n] : 0.f;
            #pragma unroll 8
            for (int p = 0; p < 32; p++) {
                int r = (tid >> 6) + p * 4;
                int m = m0 + r;
                if (m >= M) break;
                float v = epi[r * LDST + nl];
                if (EPI == 1) {
                    v += bn_;
                    v = 0.5f * v * (1.f + erff(v * 0.70710678118654752f));
                } else if (EPI == 2) {
                    v += Dm[(long long)m * ldc + n];
                } else if (EPI == 3) {
                    v += bn_ + Dm[(long long)m * ldc + n];
                }
                if (OUTH)
                    ((__half*)Cv)[(long long)m * ldc + n] = __float2half_rn(v);
                else
                    ((float*)Cv)[(long long)m * ldc + n] = v;
            }
        }
        if (h == 0) __syncthreads();
    }
}

// ---------------- classifier + final softmax: one block per batch ------------
__global__ void classifier_kernel(const float* __restrict__ hbuf,
                                  const float* __restrict__ Wc,
                                  const float* __restrict__ bc,
                                  float* __restrict__ out) {
    int b = blockIdx.x;
    int tid = threadIdx.x;  // 256
    __shared__ float xs[EE];
    __shared__ float lg[CC];
    __shared__ float red[256];

    const float* xr = hbuf + (long long)b * SS * EE;  // row s=0
    for (int i = tid; i < EE; i += 256) xs[i] = xr[i];
    __syncthreads();

    for (int c = tid; c < CC; c += 256) {
        float acc = bc[c];
        for (int e = 0; e < EE; e++) acc += xs[e] * Wc[(long long)e * CC + c];
        lg[c] = acc;
    }
    __syncthreads();

    float m = -1e30f;
    for (int c = tid; c < CC; c += 256) m = fmaxf(m, lg[c]);
    red[tid] = m; __syncthreads();
    for (int st = 128; st > 0; st >>= 1) {
        if (tid < st) red[tid] = fmaxf(red[tid], red[tid + st]);
        __syncthreads();
    }
    m = red[0];
    __syncthreads();

    float sum = 0.f;
    for (int c = tid; c < CC; c += 256) {
        float e = expf(lg[c] - m);
        lg[c] = e; sum += e;
    }
    red[tid] = sum; __syncthreads();
    for (int st = 128; st > 0; st >>= 1) {
        if (tid < st) red[tid] += red[tid + st];
        __syncthreads();
    }
    float inv = 1.f / red[0];
    for (int c = tid; c < CC; c += 256)
        out[(long long)b * CC + c] = lg[c] * inv;
}

// ---------------- host orchestration ----------------------------------------
extern "C" void kernel_launch(void* const* d_in, const int* in_sizes, int n_in,
                              void* d_out, int out_size) {
    const float* x     = (const float*)d_in[0];
    const float* Wk    = (const float*)d_in[1];
    const float* Wq    = (const float*)d_in[2];
    const float* Wv    = (const float*)d_in[3];
    const float* Wconv = (const float*)d_in[4];
    const float* ln1_w = (const float*)d_in[5];
    const float* ln1_b = (const float*)d_in[6];
    const float* ln2_w = (const float*)d_in[7];
    const float* ln2_b = (const float*)d_in[8];
    const float* W1    = (const float*)d_in[9];
    const float* b1    = (const float*)d_in[10];
    const float* W2    = (const float*)d_in[11];
    const float* b2    = (const float*)d_in[12];
    const float* Wc    = (const float*)d_in[13];
    const float* bc    = (const float*)d_in[14];
    float* out = (float*)d_out;

    float *ph, *pres1;
    __half *pxnh, *pqkvh, *poh, *pffh, *pwqkv, *pwcv, *pw1, *pw2;
    cudaGetSymbolAddress((void**)&ph,     g_h);
    cudaGetSymbolAddress((void**)&pres1,  g_res1);
    cudaGetSymbolAddress((void**)&pxnh,   g_xnh);
    cudaGetSymbolAddress((void**)&pqkvh,  g_qkvh);
    cudaGetSymbolAddress((void**)&poh,    g_oh);
    cudaGetSymbolAddress((void**)&pffh,   g_ffh);
    cudaGetSymbolAddress((void**)&pwqkv,  g_wqkv);
    cudaGetSymbolAddress((void**)&pwcv,   g_wcv);
    cudaGetSymbolAddress((void**)&pw1,    g_w1);
    cudaGetSymbolAddress((void**)&pw2,    g_w2);

    cudaFuncSetAttribute(fused_attn_kernel,
                         cudaFuncAttributeMaxDynamicSharedMemorySize,
                         ATTN_SMEM);
    cudaFuncSetAttribute(hgemm_kernel<0, true>,
                         cudaFuncAttributeMaxDynamicSharedMemorySize, HG_SMEM);
    cudaFuncSetAttribute(hgemm_kernel<1, true>,
                         cudaFuncAttributeMaxDynamicSharedMemorySize, HG_SMEM);
    cudaFuncSetAttribute(hgemm_kernel<2, false>,
                         cudaFuncAttributeMaxDynamicSharedMemorySize, HG_SMEM);
    cudaFuncSetAttribute(hgemm_kernel<3, false>,
                         cudaFuncAttributeMaxDynamicSharedMemorySize, HG_SMEM);

    cudaMemcpyAsync(ph, x, sizeof(float) * (size_t)BS * EE,
                    cudaMemcpyDeviceToDevice);

    // ---- weight conversion pre-pass (vectorized) ----
    {
        long long nq8 = (3LL * LL * HH * EE * DHH) / 8;
        pack_qkv_kernel<<<(int)((nq8 + 255) / 256), 256>>>(Wq, Wk, Wv, pwqkv);
        int ncv8 = LL * EE * EE / 8;
        cvt_f2h_kernel<<<(ncv8 + 255) / 256, 256>>>(Wconv, pwcv, ncv8);
        int n18 = LL * EE * FF_ / 8;
        cvt_f2h_kernel<<<(n18 + 255) / 256, 256>>>(W1, pw1, n18);
        cvt_f2h_kernel<<<(n18 + 255) / 256, 256>>>(W2, pw2, n18);
    }

    const float inv_scale = 1.f / sqrtf((float)SS);
    const int MT = (BS + 127) / 128;  // 50 row tiles
    const int LNB = (BS + 7) / 8;     // warp-per-row LN blocks

    for (int l = 0; l < LL; l++) {
        const __half* wqkv_l = pwqkv + (long long)l * EE * NQKV;
        const __half* wcv_l  = pwcv + (long long)l * EE * EE;
        const __half* w1_l   = pw1 + (long long)l * EE * FF_;
        const __half* w2_l   = pw2 + (long long)l * FF_ * EE;
        const float* b1_l = b1 + (long long)l * FF_;
        const float* b2_l = b2 + (long long)l * EE;

        // LN1 -> half
        layernorm_kernel<<<LNB, 256>>>(ph, ln1_w + l * EE, ln1_b + l * EE,
                                       pxnh);

        // packed QKV: [6304 x 768] @ [768 x 2304] -> half
        {
            dim3 g(NQKV / 128, MT, 1);
            hgemm_kernel<0, true><<<g, 256, HG_SMEM>>>(
                pxnh, wqkv_l, pqkvh, nullptr, nullptr,
                BS, NQKV, EE, EE, NQKV, NQKV);
        }

        // fused attention: QK^T -> softmax -> PV, all in smem
        {
            dim3 g((SS + 63) / 64, BB * HH);
            fused_attn_kernel<<<g, 256, ATTN_SMEM>>>(pqkvh, poh, inv_scale);
        }

        // res1 = O @ Wconv + h   (fp32 out)
        {
            dim3 g(EE / 128, MT, 1);
            hgemm_kernel<2, false><<<g, 256, HG_SMEM>>>(
                poh, wcv_l, pres1, nullptr, ph,
                BS, EE, EE, EE, EE, EE);
        }

        // LN2 -> half
        layernorm_kernel<<<LNB, 256>>>(pres1, ln2_w + l * EE, ln2_b + l * EE,
                                       pxnh);

        // FF1 = gelu(xn2 @ W1 + b1) -> half
        {
            dim3 g(FF_ / 128, MT, 1);
            hgemm_kernel<1, true><<<g, 256, HG_SMEM>>>(
                pxnh, w1_l, pffh, b1_l, nullptr,
                BS, FF_, EE, EE, FF_, FF_);
        }

        // h = FF1 @ W2 + b2 + res1  (fp32 out)
        {
            dim3 g(EE / 128, MT, 1);
            hgemm_kernel<3, false><<<g, 256, HG_SMEM>>>(
                pffh, w2_l, ph, b2_l, pres1,
                BS, EE, FF_, FF_, EE, EE);
        }
    }

    // classifier + softmax
    classifier_kernel<<<BB, 256>>>(ph, Wc, bc, out);
}